// round 13
// baseline (speedup 1.0000x reference)
#include <cuda_runtime.h>
#include <cuda_bf16.h>
#include <cuda_fp16.h>
#include <math.h>
#include <stdint.h>

// ---------------- problem dims ----------------
#define B_   8
#define S_   4096
#define D_   512
#define H_   1024
#define Kc_  4
#define CS_  64
#define NC_  64
#define BS_  (B_ * S_)
#define R_   512
#define ERR_CLIP  1.0f
#define GRAD_CLIP 1.0f
#define SCALE_    0.03125f

typedef __nv_bfloat16 bf16;
typedef __nv_bfloat162 bf162;
typedef __half hf;

// ---------------- device scratch ----------------
__device__ float g_proj[(size_t)BS_ * D_];
__device__ float g_vc  [(size_t)BS_ * D_];
__device__ float g_ych [(size_t)BS_ * D_];
__device__ float g_sd  [(size_t)R_ * H_];
__device__ float g_Wd1 [(size_t)H_ * D_];
__device__ float g_M1  [(size_t)H_ * D_];
__device__ float g_Wd2 [(size_t)D_ * H_];
__device__ float g_M2  [(size_t)D_ * H_];
__device__ float g_alpha[NC_];
__device__ float g_lrg [NC_];
__device__ float g_eta [NC_];
__device__ bf16 g_xh [(size_t)BS_ * D_];
__device__ bf16 g_xl [(size_t)BS_ * D_];
__device__ bf16 g_kch[(size_t)BS_ * D_];
__device__ bf16 g_kcl[(size_t)BS_ * D_];
__device__ hf   g_qf [(size_t)BS_ * D_];
__device__ hf   g_yf [(size_t)BS_ * D_];
__device__ bf16 g_a1h[(size_t)R_ * H_];
__device__ bf16 g_a1l[(size_t)R_ * H_];
__device__ bf16 g_d2h[(size_t)R_ * D_];
__device__ bf16 g_d2l[(size_t)R_ * D_];
__device__ bf16 g_d1h[(size_t)R_ * H_];
__device__ bf16 g_d1l[(size_t)R_ * H_];
__device__ hf   g_tbf[(size_t)R_ * H_];
__device__ bf16 g_E1h[(size_t)H_ * D_];
__device__ bf16 g_E1l[(size_t)H_ * D_];
__device__ hf   g_E1f[(size_t)H_ * D_];
__device__ bf16 g_E2h[(size_t)D_ * H_];
__device__ bf16 g_E2l[(size_t)D_ * H_];
__device__ hf   g_E2f[(size_t)D_ * H_];
__device__ bf16 g_Wkh[(size_t)D_ * D_];
__device__ bf16 g_Wkl[(size_t)D_ * D_];
__device__ bf16 g_Wvh[(size_t)D_ * D_];
__device__ bf16 g_Wvl[(size_t)D_ * D_];
__device__ bf16 g_Wqh[(size_t)D_ * D_];
__device__ bf16 g_Wql[(size_t)D_ * D_];
__device__ hf   g_Wof[(size_t)D_ * D_];

// ---------------- helpers ----------------
__device__ __forceinline__ float sigm(float x) { return 1.0f / (1.0f + __expf(-x)); }

__device__ __forceinline__ uint32_t smem_u32(const void* p) {
    uint32_t a;
    asm("{ .reg .u64 t; cvta.to.shared.u64 t, %1; cvt.u32.u64 %0, t; }" : "=r"(a) : "l"(p));
    return a;
}
__device__ __forceinline__ void ldsm4(uint32_t* r, uint32_t a) {
    asm volatile("ldmatrix.sync.aligned.m8n8.x4.shared.b16 {%0,%1,%2,%3}, [%4];"
        : "=r"(r[0]), "=r"(r[1]), "=r"(r[2]), "=r"(r[3]) : "r"(a));
}
__device__ __forceinline__ void ldsm4t(uint32_t* r, uint32_t a) {
    asm volatile("ldmatrix.sync.aligned.m8n8.x4.trans.shared.b16 {%0,%1,%2,%3}, [%4];"
        : "=r"(r[0]), "=r"(r[1]), "=r"(r[2]), "=r"(r[3]) : "r"(a));
}
__device__ __forceinline__ void mma16816(float* c, const uint32_t* a, uint32_t b0, uint32_t b1) {
    asm volatile("mma.sync.aligned.m16n8k16.row.col.f32.bf16.bf16.f32 "
        "{%0,%1,%2,%3}, {%4,%5,%6,%7}, {%8,%9}, {%0,%1,%2,%3};"
        : "+f"(c[0]), "+f"(c[1]), "+f"(c[2]), "+f"(c[3])
        : "r"(a[0]), "r"(a[1]), "r"(a[2]), "r"(a[3]), "r"(b0), "r"(b1));
}
__device__ __forceinline__ void mma16816h(float* c, const uint32_t* a, uint32_t b0, uint32_t b1) {
    asm volatile("mma.sync.aligned.m16n8k16.row.col.f32.f16.f16.f32 "
        "{%0,%1,%2,%3}, {%4,%5,%6,%7}, {%8,%9}, {%0,%1,%2,%3};"
        : "+f"(c[0]), "+f"(c[1]), "+f"(c[2]), "+f"(c[3])
        : "r"(a[0]), "r"(a[1]), "r"(a[2]), "r"(a[3]), "r"(b0), "r"(b1));
}
__device__ __forceinline__ void cpa(uint32_t dst, const void* src) {
    asm volatile("cp.async.cg.shared.global [%0], [%1], 16;" :: "r"(dst), "l"(src));
}
#define CP_COMMIT() asm volatile("cp.async.commit_group;" ::: "memory")
#define CP_WAIT(n)  asm volatile("cp.async.wait_group %0;" :: "n"(n) : "memory")

__device__ __forceinline__ void wr_hl(bf16* Ch, bf16* Cl, size_t idx, float v0, float v1)
{
    bf162 h(__float2bfloat16_rn(v0), __float2bfloat16_rn(v1));
    bf162 l(__float2bfloat16_rn(v0 - __bfloat162float(h.x)),
            __float2bfloat16_rn(v1 - __bfloat162float(h.y)));
    *(bf162*)(Ch + idx) = h;
    *(bf162*)(Cl + idx) = l;
}

// ---------------- tile loader (128-thread cooperative, one 64x64 16-bit tile) --------
template <bool TR>
__device__ __forceinline__ void load_tile(uint32_t sbase, const bf16* __restrict__ g,
                                          int org, int ld, int k0, int t)
{
    const int row = t >> 1;
    const int cb = (t & 1) << 2;
    const bf16* src = TR ? (g + (size_t)(k0 + row) * ld + org + cb * 8)
                         : (g + (size_t)(org + row) * ld + k0 + cb * 8);
#pragma unroll
    for (int i = 0; i < 4; i++) {
        const int c = cb + i;
        cpa(sbase + row * 128 + ((c ^ (row & 7)) << 4), src + i * 8);
    }
}

__device__ __forceinline__ void load_chunk4(uint32_t db,
    const bf16* __restrict__ Ah, const bf16* __restrict__ Al,
    const bf16* __restrict__ Bh, const bf16* __restrict__ Bl,
    int m0, int n0, int ldA, int ldB, int k0, int tl, bool AT, bool BT)
{
    if (AT) { load_tile<true >(db, Ah, m0, ldA, k0, tl); load_tile<true >(db + 8192, Al, m0, ldA, k0, tl); }
    else    { load_tile<false>(db, Ah, m0, ldA, k0, tl); load_tile<false>(db + 8192, Al, m0, ldA, k0, tl); }
    if (BT) { load_tile<true >(db + 16384, Bh, n0, ldB, k0, tl); load_tile<true >(db + 24576, Bl, n0, ldB, k0, tl); }
    else    { load_tile<false>(db + 16384, Bh, n0, ldB, k0, tl); load_tile<false>(db + 24576, Bl, n0, ldB, k0, tl); }
}

// ---------------- fragment loads ----------------
template <bool AT, bool BT>
__device__ __forceinline__ void load_frags(uint32_t ab, int ko, int wm, int wn, int lane,
    uint32_t (&ah)[2][4], uint32_t (&al)[2][4], uint32_t (&bh)[2][4], uint32_t (&bl)[2][4])
{
#pragma unroll
    for (int i = 0; i < 2; i++) {
        const int mf = wm * 32 + i * 16;
        uint32_t off;
        if (!AT) {
            const int row = mf + (lane & 7) + ((lane & 8) ? 8 : 0);
            const int ck = (ko >> 3) + ((lane >> 4) & 1);
            off = row * 128 + ((ck ^ (row & 7)) << 4);
            ldsm4(ah[i], ab + off);
            ldsm4(al[i], ab + 8192 + off);
        } else {
            const int row = ko + (lane & 7) + ((lane & 16) ? 8 : 0);
            const int ck = (mf >> 3) + ((lane >> 3) & 1);
            off = row * 128 + ((ck ^ (row & 7)) << 4);
            ldsm4t(ah[i], ab + off);
            ldsm4t(al[i], ab + 8192 + off);
        }
    }
#pragma unroll
    for (int jp = 0; jp < 2; jp++) {
        const int nf = wn * 32 + jp * 16;
        uint32_t off;
        if (!BT) {
            const int row = nf + (lane & 7) + ((lane & 16) ? 8 : 0);
            const int ck = (ko >> 3) + ((lane >> 3) & 1);
            off = row * 128 + ((ck ^ (row & 7)) << 4);
            ldsm4(bh[jp], ab + 16384 + off);
            ldsm4(bl[jp], ab + 24576 + off);
        } else {
            const int row = ko + (lane & 7) + ((lane & 8) ? 8 : 0);
            const int ck = (nf >> 3) + ((lane >> 4) & 1);
            off = row * 128 + ((ck ^ (row & 7)) << 4);
            ldsm4t(bh[jp], ab + 16384 + off);
            ldsm4t(bl[jp], ab + 24576 + off);
        }
    }
}

// fp16 single-pass fragments (NT direct only; A @ab, B @ab+8192)
__device__ __forceinline__ void load_frags_f16(uint32_t ab, int ko, int wm, int wn, int lane,
    uint32_t (&a)[2][4], uint32_t (&b)[2][4])
{
#pragma unroll
    for (int i = 0; i < 2; i++) {
        const int row = wm * 32 + i * 16 + (lane & 7) + ((lane & 8) ? 8 : 0);
        const int ck = (ko >> 3) + ((lane >> 4) & 1);
        ldsm4(a[i], ab + row * 128 + ((ck ^ (row & 7)) << 4));
    }
#pragma unroll
    for (int jp = 0; jp < 2; jp++) {
        const int row = wn * 32 + jp * 16 + (lane & 7) + ((lane & 16) ? 8 : 0);
        const int ck = (ko >> 3) + ((lane >> 3) & 1);
        ldsm4(b[jp], ab + 8192 + row * 128 + ((ck ^ (row & 7)) << 4));
    }
}

// ---------------- one K=64 chunk of MMAs, register-double-buffered ----------------
template <bool AT, bool BT>
__device__ __forceinline__ void mma_chunk(uint32_t ab, float acc[2][4][4],
                                          int wm, int wn, int lane)
{
    uint32_t ah[2][2][4], al[2][2][4], bh[2][2][4], bl[2][2][4];
    load_frags<AT, BT>(ab, 0, wm, wn, lane, ah[0], al[0], bh[0], bl[0]);
#pragma unroll
    for (int koi = 0; koi < 4; koi++) {
        const int cur = koi & 1;
        if (koi < 3)
            load_frags<AT, BT>(ab, (koi + 1) << 4, wm, wn, lane,
                               ah[cur ^ 1], al[cur ^ 1], bh[cur ^ 1], bl[cur ^ 1]);
#pragma unroll
        for (int i = 0; i < 2; i++)
#pragma unroll
            for (int j = 0; j < 4; j++) {
                const int jp = j >> 1, wv = (j & 1) << 1;
                mma16816(acc[i][j], ah[cur][i], bh[cur][jp][wv], bh[cur][jp][wv + 1]);
                mma16816(acc[i][j], ah[cur][i], bl[cur][jp][wv], bl[cur][jp][wv + 1]);
                mma16816(acc[i][j], al[cur][i], bh[cur][jp][wv], bh[cur][jp][wv + 1]);
            }
    }
}

__device__ __forceinline__ void mma_chunk_f16(uint32_t ab, float acc[2][4][4],
                                              int wm, int wn, int lane)
{
    uint32_t a[2][2][4], b[2][2][4];
    load_frags_f16(ab, 0, wm, wn, lane, a[0], b[0]);
#pragma unroll
    for (int koi = 0; koi < 4; koi++) {
        const int cur = koi & 1;
        if (koi < 3)
            load_frags_f16(ab, (koi + 1) << 4, wm, wn, lane, a[cur ^ 1], b[cur ^ 1]);
#pragma unroll
        for (int i = 0; i < 2; i++)
#pragma unroll
            for (int j = 0; j < 4; j++) {
                const int jp = j >> 1, wv = (j & 1) << 1;
                mma16816h(acc[i][j], a[cur][i], b[cur][jp][wv], b[cur][jp][wv + 1]);
            }
    }
}

// ---------------- 4-warp GEMM mainloops ----------------
template <bool AT, bool BT>
__device__ __forceinline__ void gemm_main(
    const bf16* __restrict__ Ah, const bf16* __restrict__ Al,
    const bf16* __restrict__ Bh, const bf16* __restrict__ Bl,
    int m0, int n0, int ldA, int ldB, int K,
    uint32_t sb, int t, int wm, int wn, int lane, float acc[2][4][4])
{
    const int nch = K >> 6;
    load_chunk4(sb, Ah, Al, Bh, Bl, m0, n0, ldA, ldB, 0, t, AT, BT);
    CP_COMMIT();
    for (int ch = 0; ch < nch; ch++) {
        if (ch + 1 < nch) {
            load_chunk4(sb + ((ch + 1) & 1) * 32768, Ah, Al, Bh, Bl,
                        m0, n0, ldA, ldB, (ch + 1) << 6, t, AT, BT);
            CP_COMMIT();
            CP_WAIT(1);
        } else {
            CP_WAIT(0);
        }
        __syncthreads();
        mma_chunk<AT, BT>(sb + (ch & 1) * 32768, acc, wm, wn, lane);
        __syncthreads();
    }
}

__device__ __forceinline__ void gemm_main_f16(
    const hf* __restrict__ A, const hf* __restrict__ B,
    int m0, int n0, int ldA, int ldB, int K,
    uint32_t sb, int t, int wm, int wn, int lane, float acc[2][4][4])
{
    const int nch = K >> 6;
    load_tile<false>(sb,        (const bf16*)A, m0, ldA, 0, t);
    load_tile<false>(sb + 8192, (const bf16*)B, n0, ldB, 0, t);
    CP_COMMIT();
    for (int ch = 0; ch < nch; ch++) {
        if (ch + 1 < nch) {
            const uint32_t nb = sb + ((ch + 1) & 1) * 16384;
            const int k0 = (ch + 1) << 6;
            load_tile<false>(nb,        (const bf16*)A, m0, ldA, k0, t);
            load_tile<false>(nb + 8192, (const bf16*)B, n0, ldB, k0, t);
            CP_COMMIT();
            CP_WAIT(1);
        } else {
            CP_WAIT(0);
        }
        __syncthreads();
        mma_chunk_f16(sb + (ch & 1) * 16384, acc, wm, wn, lane);
        __syncthreads();
    }
}

// ---------------- 8-warp GEMM mainloops (warp-group split-K) ----------------
template <bool AT, bool BT>
__device__ __forceinline__ void gemm_main8(
    const bf16* __restrict__ Ah, const bf16* __restrict__ Al,
    const bf16* __restrict__ Bh, const bf16* __restrict__ Bl,
    int m0, int n0, int ldA, int ldB, int K,
    uint32_t sb, int t, int wg, int wm, int wn, int lane, float acc[2][4][4])
{
    const int npair = K >> 7;
    const int tl = t & 127;
    const int which = t >> 7;
    load_chunk4(sb + which * 32768, Ah, Al, Bh, Bl, m0, n0, ldA, ldB,
                which << 6, tl, AT, BT);
    CP_COMMIT();
    for (int p = 0; p < npair; p++) {
        if (p + 1 < npair) {
            load_chunk4(sb + ((p + 1) & 1) * 65536 + which * 32768, Ah, Al, Bh, Bl,
                        m0, n0, ldA, ldB, ((p + 1) << 7) + (which << 6), tl, AT, BT);
            CP_COMMIT();
            CP_WAIT(1);
        } else {
            CP_WAIT(0);
        }
        __syncthreads();
        mma_chunk<AT, BT>(sb + (p & 1) * 65536 + wg * 32768, acc, wm, wn, lane);
        __syncthreads();
    }
}

__device__ __forceinline__ void gemm_main8_f16(
    const hf* __restrict__ A, const hf* __restrict__ B,
    int m0, int n0, int ldA, int ldB, int K,
    uint32_t sb, int t, int wg, int wm, int wn, int lane, float acc[2][4][4])
{
    const int npair = K >> 7;
    const int tl = t & 127;
    const int which = t >> 7;
    {
        const uint32_t db = sb + which * 16384;
        load_tile<false>(db,        (const bf16*)A, m0, ldA, which << 6, tl);
        load_tile<false>(db + 8192, (const bf16*)B, n0, ldB, which << 6, tl);
    }
    CP_COMMIT();
    for (int p = 0; p < npair; p++) {
        if (p + 1 < npair) {
            const uint32_t db = sb + ((p + 1) & 1) * 32768 + which * 16384;
            const int k0 = ((p + 1) << 7) + (which << 6);
            load_tile<false>(db,        (const bf16*)A, m0, ldA, k0, tl);
            load_tile<false>(db + 8192, (const bf16*)B, n0, ldB, k0, tl);
            CP_COMMIT();
            CP_WAIT(1);
        } else {
            CP_WAIT(0);
        }
        __syncthreads();
        mma_chunk_f16(sb + (p & 1) * 32768 + wg * 16384, acc, wm, wn, lane);
        __syncthreads();
    }
}

__device__ __forceinline__ void reduce8(float acc[2][4][4], float* red,
                                        int wg, int wi, int lane)
{
    if (wg == 1) {
#pragma unroll
        for (int i = 0; i < 2; i++)
#pragma unroll
            for (int j = 0; j < 4; j++) {
                const int r = i * 16 + (lane >> 2);
                const int cc = j * 8 + ((lane & 3) << 1);
                *(float2*)&red[wi * 1024 + r * 32 + cc] = make_float2(acc[i][j][0], acc[i][j][1]);
                *(float2*)&red[wi * 1024 + (r + 8) * 32 + cc] = make_float2(acc[i][j][2], acc[i][j][3]);
            }
    }
    __syncthreads();
    if (wg == 0) {
#pragma unroll
        for (int i = 0; i < 2; i++)
#pragma unroll
            for (int j = 0; j < 4; j++) {
                const int r = i * 16 + (lane >> 2);
                const int cc = j * 8 + ((lane & 3) << 1);
                const float2 v0 = *(const float2*)&red[wi * 1024 + r * 32 + cc];
                const float2 v1 = *(const float2*)&red[wi * 1024 + (r + 8) * 32 + cc];
                acc[i][j][0] += v0.x; acc[i][j][1] += v0.y;
                acc[i][j][2] += v1.x; acc[i][j][3] += v1.y;
            }
    }
}

// ---------------- epilogues ----------------
// EPI 0: C = acc (fp32)
// EPI 1: Ch/Cl = silu(acc), U1 = silu'(acc)
// EPI 2: Ch/Cl = SCALE*clip(acc - X1)
// EPI 3: Ch/Cl = acc * X1
// EPI 4: update M/Wd; Ch/Cl = X1+wd ; F = fp16(X1+wd)
// EPI 6: F = fp16(silu(acc))
template <int EPI>
__device__ __forceinline__ void epi_store(const float acc[2][4][4],
    int m0, int n0, int N, int wm, int wn, int lane,
    float* __restrict__ C, bf16* __restrict__ Ch, bf16* __restrict__ Cl,
    const float* __restrict__ X1, float* __restrict__ U1, float* __restrict__ U2,
    float ga, float gl, float ge, hf* __restrict__ F)
{
#pragma unroll
    for (int i = 0; i < 2; i++)
#pragma unroll
        for (int j = 0; j < 4; j++) {
            const float* a = acc[i][j];
            const int mr0 = m0 + wm * 32 + i * 16 + (lane >> 2);
            const int nc  = n0 + wn * 32 + j * 8 + ((lane & 3) << 1);
            const size_t i0 = (size_t)mr0 * N + nc;
            const size_t i1 = (size_t)(mr0 + 8) * N + nc;

            if (EPI == 0) {
                *(float2*)(C + i0) = make_float2(a[0], a[1]);
                *(float2*)(C + i1) = make_float2(a[2], a[3]);
            } else if (EPI == 1) {
                const float s0 = sigm(a[0]), s1 = sigm(a[1]);
                const float s2 = sigm(a[2]), s3 = sigm(a[3]);
                wr_hl(Ch, Cl, i0, a[0] * s0, a[1] * s1);
                wr_hl(Ch, Cl, i1, a[2] * s2, a[3] * s3);
                *(float2*)(U1 + i0) = make_float2(s0 * (1.f + a[0] * (1.f - s0)),
                                                  s1 * (1.f + a[1] * (1.f - s1)));
                *(float2*)(U1 + i1) = make_float2(s2 * (1.f + a[2] * (1.f - s2)),
                                                  s3 * (1.f + a[3] * (1.f - s3)));
            } else if (EPI == 2) {
                const float2 v0 = *(const float2*)(X1 + i0);
                const float2 v1 = *(const float2*)(X1 + i1);
                wr_hl(Ch, Cl, i0,
                      SCALE_ * fminf(fmaxf(a[0] - v0.x, -ERR_CLIP), ERR_CLIP),
                      SCALE_ * fminf(fmaxf(a[1] - v0.y, -ERR_CLIP), ERR_CLIP));
                wr_hl(Ch, Cl, i1,
                      SCALE_ * fminf(fmaxf(a[2] - v1.x, -ERR_CLIP), ERR_CLIP),
                      SCALE_ * fminf(fmaxf(a[3] - v1.y, -ERR_CLIP), ERR_CLIP));
            } else if (EPI == 3) {
                const float2 v0 = *(const float2*)(X1 + i0);
                const float2 v1 = *(const float2*)(X1 + i1);
                wr_hl(Ch, Cl, i0, a[0] * v0.x, a[1] * v0.y);
                wr_hl(Ch, Cl, i1, a[2] * v1.x, a[3] * v1.y);
            } else if (EPI == 4) {
                float2 mo0 = *(float2*)(U1 + i0), mo1 = *(float2*)(U1 + i1);
                float2 wd0 = *(float2*)(U2 + i0), wd1 = *(float2*)(U2 + i1);
                mo0.x = ge * mo0.x - gl * fminf(fmaxf(a[0], -GRAD_CLIP), GRAD_CLIP);
                mo0.y = ge * mo0.y - gl * fminf(fmaxf(a[1], -GRAD_CLIP), GRAD_CLIP);
                mo1.x = ge * mo1.x - gl * fminf(fmaxf(a[2], -GRAD_CLIP), GRAD_CLIP);
                mo1.y = ge * mo1.y - gl * fminf(fmaxf(a[3], -GRAD_CLIP), GRAD_CLIP);
                wd0.x = (1.f - ga) * wd0.x + mo0.x;
                wd0.y = (1.f - ga) * wd0.y + mo0.y;
                wd1.x = (1.f - ga) * wd1.x + mo1.x;
                wd1.y = (1.f - ga) * wd1.y + mo1.y;
                *(float2*)(U1 + i0) = mo0; *(float2*)(U1 + i1) = mo1;
                *(float2*)(U2 + i0) = wd0; *(float2*)(U2 + i1) = wd1;
                const float2 w0 = *(const float2*)(X1 + i0);
                const float2 w1 = *(const float2*)(X1 + i1);
                wr_hl(Ch, Cl, i0, w0.x + wd0.x, w0.y + wd0.y);
                wr_hl(Ch, Cl, i1, w1.x + wd1.x, w1.y + wd1.y);
                *(__half2*)(F + i0) = __floats2half2_rn(w0.x + wd0.x, w0.y + wd0.y);
                *(__half2*)(F + i1) = __floats2half2_rn(w1.x + wd1.x, w1.y + wd1.y);
            } else { // EPI 6
                *(__half2*)(F + i0) = __floats2half2_rn(a[0] * sigm(a[0]), a[1] * sigm(a[1]));
                *(__half2*)(F + i1) = __floats2half2_rn(a[2] * sigm(a[2]), a[3] * sigm(a[3]));
            }
        }
}

#define GSMEM   65536
#define GSMEM8  131072
#define GSMEMF  32768

// ---------------- 4-warp solo GEMM kernel (bf16x3) ----------------
template <int EPI, bool AT, bool BT>
__global__ void __launch_bounds__(128)
mma_gemm(const bf16* __restrict__ Ah, const bf16* __restrict__ Al,
         const bf16* __restrict__ Bh, const bf16* __restrict__ Bl,
         float* __restrict__ C, bf16* __restrict__ Ch, bf16* __restrict__ Cl,
         const float* __restrict__ X1, float* __restrict__ U1, float* __restrict__ U2,
         int M, int N, int K, int gate)
{
    extern __shared__ __align__(1024) char smem[];
    const int t = threadIdx.x, lane = t & 31, w = t >> 5;
    const int wm = w & 1, wn = w >> 1;
    const int m0 = blockIdx.y << 6, n0 = blockIdx.x << 6;
    const uint32_t sb = smem_u32(smem);
    float acc[2][4][4] = {};
    gemm_main<AT, BT>(Ah, Al, Bh, Bl, m0, n0, AT ? M : K, BT ? N : K, K,
                      sb, t, wm, wn, lane, acc);
    epi_store<EPI>(acc, m0, n0, N, wm, wn, lane, C, Ch, Cl, X1, U1, U2,
                   0.f, 0.f, 0.f, nullptr);
}

// ---------------- 4-warp solo fp16 GEMM kernel ----------------
template <int EPI>
__global__ void __launch_bounds__(128)
mma_gemm_f16k(const hf* __restrict__ A, const hf* __restrict__ B,
              float* __restrict__ C, hf* __restrict__ F, int M, int N, int K)
{
    extern __shared__ __align__(1024) char smem[];
    const int t = threadIdx.x, lane = t & 31, w = t >> 5;
    const int wm = w & 1, wn = w >> 1;
    const int m0 = blockIdx.y << 6, n0 = blockIdx.x << 6;
    const uint32_t sb = smem_u32(smem);
    float acc[2][4][4] = {};
    gemm_main_f16(A, B, m0, n0, K, K, K, sb, t, wm, wn, lane, acc);
    epi_store<EPI>(acc, m0, n0, N, wm, wn, lane, C, nullptr, nullptr,
                   nullptr, nullptr, nullptr, 0.f, 0.f, 0.f, F);
}

// ---------------- 8-warp solo GEMM kernel (bf16x3, prologue) ----------------
template <int EPI, bool AT, bool BT>
__global__ void __launch_bounds__(256)
mma_gemm8(const bf16* __restrict__ Ah, const bf16* __restrict__ Al,
          const bf16* __restrict__ Bh, const bf16* __restrict__ Bl,
          float* __restrict__ C, bf16* __restrict__ Ch, bf16* __restrict__ Cl,
          const float* __restrict__ X1, float* __restrict__ U1, float* __restrict__ U2,
          int M, int N, int K, int gate)
{
    extern __shared__ __align__(1024) char smem[];
    const int t = threadIdx.x, lane = t & 31, w = t >> 5;
    const int wg = w >> 2, wi = w & 3;
    const int wm = wi & 1, wn = wi >> 1;
    const int m0 = blockIdx.y << 6, n0 = blockIdx.x << 6;
    const uint32_t sb = smem_u32(smem);
    float acc[2][4][4] = {};
    gemm_main8<AT, BT>(Ah, Al, Bh, Bl, m0, n0, AT ? M : K, BT ? N : K, K,
                       sb, t, wg, wm, wn, lane, acc);
    reduce8(acc, (float*)smem, wg, wi, lane);
    if (wg == 0)
        epi_store<EPI>(acc, m0, n0, N, wm, wn, lane, C, Ch, Cl, X1, U1, U2,
                       0.f, 0.f, 0.f, nullptr);
}

// ---------------- fused dual-update kernel (4-warp; 256 CTAs) ----------------
__global__ void __launch_bounds__(128)
mma_update_dual(const bf16* __restrict__ d2h, const bf16* __restrict__ d2l,
                const bf16* __restrict__ a1h, const bf16* __restrict__ a1l,
                const bf16* __restrict__ d1h, const bf16* __restrict__ d1l,
                const bf16* __restrict__ kchp, const bf16* __restrict__ kclp,
                const float* __restrict__ W2, float* __restrict__ M2,
                float* __restrict__ Wd2, bf16* __restrict__ E2h, bf16* __restrict__ E2l,
                hf* __restrict__ E2f,
                const float* __restrict__ W1, float* __restrict__ M1,
                float* __restrict__ Wd1, bf16* __restrict__ E1h, bf16* __restrict__ E1l,
                hf* __restrict__ E1f, int gate)
{
    extern __shared__ __align__(1024) char smem[];
    const int t = threadIdx.x, lane = t & 31, w = t >> 5;
    const int wm = w & 1, wn = w >> 1;
    const int bid = blockIdx.x;
    const bool segb = bid >= 128;
    const uint32_t sb = smem_u32(smem);
    const float ga = g_alpha[gate], gl = g_lrg[gate], ge = g_eta[gate];
    float acc[2][4][4] = {};
    if (!segb) {
        const int n0 = (bid & 15) << 6, m0 = (bid >> 4) << 6;
        gemm_main<true, true>(d2h, d2l, a1h, a1l, m0, n0, D_, H_, R_,
                              sb, t, wm, wn, lane, acc);
        epi_store<4>(acc, m0, n0, H_, wm, wn, lane, nullptr, E2h, E2l, W2, M2, Wd2,
                     ga, gl, ge, E2f);
    } else {
        const int r = bid - 128;
        const int n0 = (r & 7) << 6, m0 = (r >> 3) << 6;
        gemm_main<true, true>(d1h, d1l, kchp, kclp, m0, n0, H_, D_, R_,
                              sb, t, wm, wn, lane, acc);
        epi_store<4>(acc, m0, n0, D_, wm, wn, lane, nullptr, E1h, E1l, W1, M1, Wd1,
                     ga, gl, ge, E1f);
    }
}

// ---------------- dual: tb (fp16 1-pass) + a1'(c+1) (bf16x3) ----------------
// grid (16, 8 or 16): by<8 -> tb seg; by>=8 -> a1' seg
__global__ void __launch_bounds__(128)
dual_tb_a1(const hf* __restrict__ qf, const hf* __restrict__ E1f, hf* __restrict__ tbf,
           const bf16* __restrict__ knh, const bf16* __restrict__ knl,
           const bf16* __restrict__ E1h, const bf16* __restrict__ E1l,
           bf16* __restrict__ a1h, bf16* __restrict__ a1l, float* __restrict__ sd)
{
    extern __shared__ __align__(1024) char smem[];
    const int t = threadIdx.x, lane = t & 31, w = t >> 5;
    const int wm = w & 1, wn = w >> 1;
    const int by = blockIdx.y;
    const int n0 = blockIdx.x << 6;
    const uint32_t sb = smem_u32(smem);
    float acc[2][4][4] = {};
    if (by < 8) {
        const int m0 = by << 6;
        gemm_main_f16(qf, E1f, m0, n0, D_, D_, D_, sb, t, wm, wn, lane, acc);
        epi_store<6>(acc, m0, n0, H_, wm, wn, lane, nullptr, nullptr, nullptr,
                     nullptr, nullptr, nullptr, 0.f, 0.f, 0.f, tbf);
    } else {
        const int m0 = (by - 8) << 6;
        gemm_main<false, false>(knh, knl, E1h, E1l, m0, n0, D_, D_, D_,
                                sb, t, wm, wn, lane, acc);
        epi_store<1>(acc, m0, n0, H_, wm, wn, lane, nullptr, a1h, a1l,
                     nullptr, sd, nullptr, 0.f, 0.f, 0.f, nullptr);
    }
}

// ---------------- dual8: y (fp16 1-pass K=1024) + d2'(c+1) (bf16x3 K=1024) --------
// grid (8, 8 or 16): by<8 -> y seg; by>=8 -> d2' seg. 256 threads.
__global__ void __launch_bounds__(256)
dual8_y_d2(const hf* __restrict__ tbf, const hf* __restrict__ E2f,
           float* __restrict__ ych_c,
           const bf16* __restrict__ a1h, const bf16* __restrict__ a1l,
           const bf16* __restrict__ E2h, const bf16* __restrict__ E2l,
           const float* __restrict__ vcn, bf16* __restrict__ d2h, bf16* __restrict__ d2l)
{
    extern __shared__ __align__(1024) char smem[];
    const int t = threadIdx.x, lane = t & 31, w = t >> 5;
    const int wg = w >> 2, wi = w & 3;
    const int wm = wi & 1, wn = wi >> 1;
    const int by = blockIdx.y;
    const int n0 = blockIdx.x << 6;
    const uint32_t sb = smem_u32(smem);
    float acc[2][4][4] = {};
    if (by < 8) {
        const int m0 = by << 6;
        gemm_main8_f16(tbf, E2f, m0, n0, H_, H_, H_, sb, t, wg, wm, wn, lane, acc);
        reduce8(acc, (float*)smem, wg, wi, lane);
        if (wg == 0)
            epi_store<0>(acc, m0, n0, D_, wm, wn, lane, ych_c, nullptr, nullptr,
                         nullptr, nullptr, nullptr, 0.f, 0.f, 0.f, nullptr);
    } else {
        const int m0 = (by - 8) << 6;
        gemm_main8<false, false>(a1h, a1l, E2h, E2l, m0, n0, H_, H_, H_,
                                 sb, t, wg, wm, wn, lane, acc);
        reduce8(acc, (float*)smem, wg, wi, lane);
        if (wg == 0)
            epi_store<2>(acc, m0, n0, D_, wm, wn, lane, nullptr, d2h, d2l,
                         vcn, nullptr, nullptr, 0.f, 0.f, 0.f, nullptr);
    }
}

template <int EPI, bool AT, bool BT>
static void run(const bf16* Ah, const bf16* Al, const bf16* Bh, const bf16* Bl,
                float* C, bf16* Ch, bf16* Cl,
                const float* X1, float* U1, float* U2, int M, int N, int K, int gate)
{
    cudaFuncSetAttribute(mma_gemm<EPI, AT, BT>,
                         cudaFuncAttributeMaxDynamicSharedMemorySize, GSMEM);
    dim3 grid(N >> 6, M >> 6);
    mma_gemm<EPI, AT, BT><<<grid, 128, GSMEM>>>(Ah, Al, Bh, Bl, C, Ch, Cl, X1, U1, U2,
                                                M, N, K, gate);
}

template <int EPI, bool AT, bool BT>
static void run8(const bf16* Ah, const bf16* Al, const bf16* Bh, const bf16* Bl,
                 float* C, bf16* Ch, bf16* Cl,
                 const float* X1, float* U1, float* U2, int M, int N, int K, int gate)
{
    cudaFuncSetAttribute(mma_gemm8<EPI, AT, BT>,
                         cudaFuncAttributeMaxDynamicSharedMemorySize, GSMEM8);
    dim3 grid(N >> 6, M >> 6);
    mma_gemm8<EPI, AT, BT><<<grid, 256, GSMEM8>>>(Ah, Al, Bh, Bl, C, Ch, Cl, X1, U1, U2,
                                                  M, N, K, gate);
}

template <int EPI>
static void run_f16(const hf* A, const hf* B, float* C, hf* F, int M, int N, int K)
{
    cudaFuncSetAttribute(mma_gemm_f16k<EPI>,
                         cudaFuncAttributeMaxDynamicSharedMemorySize, GSMEMF);
    dim3 grid(N >> 6, M >> 6);
    mma_gemm_f16k<EPI><<<grid, 128, GSMEMF>>>(A, B, C, F, M, N, K);
}

// ---------------- misc kernels ----------------
__global__ void init_kernel(const float* __restrict__ W1, const float* __restrict__ W2)
{
    const size_t i = ((size_t)blockIdx.x * blockDim.x + threadIdx.x) * 2;
    if (i >= (size_t)H_ * D_) return;
    *(float2*)(g_Wd1 + i) = make_float2(0.f, 0.f);
    *(float2*)(g_M1  + i) = make_float2(0.f, 0.f);
    *(float2*)(g_Wd2 + i) = make_float2(0.f, 0.f);
    *(float2*)(g_M2  + i) = make_float2(0.f, 0.f);
    const float2 w1 = *(const float2*)(W1 + i);
    const float2 w2 = *(const float2*)(W2 + i);
    wr_hl(g_E1h, g_E1l, i, w1.x, w1.y);
    wr_hl(g_E2h, g_E2l, i, w2.x, w2.y);
    *(__half2*)(g_E1f + i) = __floats2half2_rn(w1.x, w1.y);
    *(__half2*)(g_E2f + i) = __floats2half2_rn(w2.x, w2.y);
}

__global__ void cvt_kernel(const float* __restrict__ s, bf16* __restrict__ h,
                           bf16* __restrict__ l, int n2)
{
    const int i = blockIdx.x * blockDim.x + threadIdx.x;
    if (i >= n2) return;
    const float2 v = ((const float2*)s)[i];
    wr_hl(h, l, (size_t)i * 2, v.x, v.y);
}

__global__ void cvt_f16_kernel(const float* __restrict__ s, hf* __restrict__ d, int n2)
{
    const int i = blockIdx.x * blockDim.x + threadIdx.x;
    if (i >= n2) return;
    const float2 v = ((const float2*)s)[i];
    *(__half2*)(d + (size_t)i * 2) = __floats2half2_rn(v.x, v.y);
}

// causal depthwise conv -> chunk-major [NC][R][D]; out: fp32 OR bf16 hi/lo OR fp16
__global__ void conv_chunk_kernel(const float* __restrict__ in, const float* __restrict__ w,
                                  const float* __restrict__ bias,
                                  bf16* __restrict__ oh, bf16* __restrict__ ol,
                                  float* __restrict__ of, hf* __restrict__ o16)
{
    const size_t i = (size_t)blockIdx.x * blockDim.x + threadIdx.x;
    if (i >= (size_t)BS_ * D_) return;
    const int d = (int)(i & (D_ - 1));
    const size_t bs = i >> 9;
    const int s = (int)(bs & (S_ - 1));
    const int b = (int)(bs >> 12);
    float acc = bias[d];
#pragma unroll
    for (int j = 0; j < Kc_; j++) {
        const int sp = s - (Kc_ - 1) + j;
        if (sp >= 0)
            acc = fmaf(w[d * Kc_ + j], in[((size_t)b * S_ + sp) * D_ + d], acc);
    }
    const int c  = s >> 6;
    const int cs = s & 63;
    const size_t o = (((size_t)c * R_ + (b * CS_ + cs)) << 9) + d;
    if (of) {
        of[o] = acc;
    } else if (o16) {
        o16[o] = __float2half_rn(acc);
    } else {
        const bf16 hv = __float2bfloat16_rn(acc);
        oh[o] = hv;
        ol[o] = __float2bfloat16_rn(acc - __bfloat162float(hv));
    }
}

__global__ void gates_kernel(const float* __restrict__ x,
                             const float* __restrict__ wd, const float* __restrict__ bd,
                             const float* __restrict__ wl, const float* __restrict__ bl,
                             const float* __restrict__ we, const float* __restrict__ be)
{
    const int c = blockIdx.x;
    const int t = threadIdx.x;
    const int b  = t >> 6;
    const int cs = t & 63;
    const float4* xr = (const float4*)(x + (((size_t)b * S_ + (size_t)c * CS_ + cs) << 9));
    const float4* w0 = (const float4*)wd;
    const float4* w1 = (const float4*)wl;
    const float4* w2 = (const float4*)we;
    float s0 = 0.f, s1 = 0.f, s2 = 0.f;
#pragma unroll 4
    for (int d = 0; d < D_ / 4; d++) {
        const float4 xv = xr[d];
        const float4 a0 = w0[d], a1 = w1[d], a2 = w2[d];
        s0 += xv.x * a0.x + xv.y * a0.y + xv.z * a0.z + xv.w * a0.w;
        s1 += xv.x * a1.x + xv.y * a1.y + xv.z * a1.z + xv.w * a1.w;
        s2 += xv.x * a2.x + xv.y * a2.y + xv.z * a2.z + xv.w * a2.w;
    }
    s0 = sigm(s0 + bd[0]);
    s1 = sigm(s1 + bl[0]);
    s2 = sigm(s2 + be[0]);

    __shared__ float r0[512], r1[512], r2[512];
    r0[t] = s0; r1[t] = s1; r2[t] = s2;
    __syncthreads();
    for (int off = 256; off > 0; off >>= 1) {
        if (t < off) { r0[t] += r0[t + off]; r1[t] += r1[t + off]; r2[t] += r2[t + off]; }
        __syncthreads();
    }
    if (t == 0) {
        g_alpha[c] = r0[0] * (1.0f / 512.0f);
        g_lrg[c]   = r1[0] * (1.0f / 512.0f);
        g_eta[c]   = r2[0] * (1.0f / 512.0f);
    }
}

// chunk-major ych -> flat [B,S,D] as fp16
__global__ void permute_y_kernel()
{
    const size_t i = (size_t)blockIdx.x * blockDim.x + threadIdx.x;
    if (i >= (size_t)BS_ * D_) return;
    const int d = (int)(i & (D_ - 1));
    const size_t rw = i >> 9;
    const int s = (int)(rw & (S_ - 1));
    const int b = (int)(rw >> 12);
    const int c  = s >> 6;
    const int cs = s & 63;
    g_yf[i] = __float2half_rn(g_ych[(((size_t)c * R_ + (b * CS_ + cs)) << 9) + d]);
}

// ---------------- entry point ----------------
extern "C" void kernel_launch(void* const* d_in, const int* in_sizes, int n_in,
                              void* d_out, int out_size)
{
    (void)in_sizes; (void)n_in; (void)out_size;
    const float* x    = (const float*)d_in[0];
    const float* Wk   = (const float*)d_in[1];
    const float* Wv   = (const float*)d_in[2];
    const float* Wq   = (const float*)d_in[3];
    const float* Wout = (const float*)d_in[4];
    const float* ckw  = (const float*)d_in[5];
    const float* ckb  = (const float*)d_in[6];
    const float* cvw  = (const float*)d_in[7];
    const float* cvb  = (const float*)d_in[8];
    const float* cqw  = (const float*)d_in[9];
    const float* cqb  = (const float*)d_in[10];
    const float* wdec = (const float*)d_in[11];
    const float* bdec = (const float*)d_in[12];
    const float* wlr  = (const float*)d_in[13];
    const float* blr  = (const float*)d_in[14];
    const float* weta = (const float*)d_in[15];
    const float* beta = (const float*)d_in[16];
    const float* W1   = (const float*)d_in[17];
    const float* W2   = (const float*)d_in[18];
    float* out = (float*)d_out;

    float *proj, *vc, *ych, *sd, *Wd1, *M1, *Wd2, *M2;
    bf16 *xh, *xl, *kch, *kcl, *a1h, *a1l, *d2h, *d2l, *d1h, *d1l;
    bf16 *E1h, *E1l, *E2h, *E2l, *Wkh, *Wkl, *Wvh, *Wvl, *Wqh, *Wql;
    hf *qf, *yf, *tbf, *E1f, *E2f, *Wof;
    cudaGetSymbolAddress((void**)&proj, g_proj);
    cudaGetSymbolAddress((void**)&vc,   g_vc);
    cudaGetSymbolAddress((void**)&ych,  g_ych);
    cudaGetSymbolAddress((void**)&sd,   g_sd);
    cudaGetSymbolAddress((void**)&Wd1,  g_Wd1);
    cudaGetSymbolAddress((void**)&M1,   g_M1);
    cudaGetSymbolAddress((void**)&Wd2,  g_Wd2);
    cudaGetSymbolAddress((void**)&M2,   g_M2);
    cudaGetSymbolAddress((void**)&xh,  g_xh);  cudaGetSymbolAddress((void**)&xl,  g_xl);
    cudaGetSymbolAddress((void**)&kch, g_kch); cudaGetSymbolAddress((void**)&kcl, g_kcl);
    cudaGetSymbolAddress((void**)&qf,  g_qf);  cudaGetSymbolAddress((void**)&yf,  g_yf);
    cudaGetSymbolAddress((void**)&a1h, g_a1h); cudaGetSymbolAddress((void**)&a1l, g_a1l);
    cudaGetSymbolAddress((void**)&d2h, g_d2h); cudaGetSymbolAddress((void**)&d2l, g_d2l);
    cudaGetSymbolAddress((void**)&d1h, g_d1h); cudaGetSymbolAddress((void**)&d1l, g_d1l);
    cudaGetSymbolAddress((void**)&tbf, g_tbf);
    cudaGetSymbolAddress((void**)&E1h, g_E1h); cudaGetSymbolAddress((void**)&E1l, g_E1l);
    cudaGetSymbolAddress((void**)&E2h, g_E2h); cudaGetSymbolAddress((void**)&E2l, g_E2l);
    cudaGetSymbolAddress((void**)&E1f, g_E1f); cudaGetSymbolAddress((void**)&E2f, g_E2f);
    cudaGetSymbolAddress((void**)&Wkh, g_Wkh); cudaGetSymbolAddress((void**)&Wkl, g_Wkl);
    cudaGetSymbolAddress((void**)&Wvh, g_Wvh); cudaGetSymbolAddress((void**)&Wvl, g_Wvl);
    cudaGetSymbolAddress((void**)&Wqh, g_Wqh); cudaGetSymbolAddress((void**)&Wql, g_Wql);
    cudaGetSymbolAddress((void**)&Wof, g_Wof);

    const int nRD = R_ * D_;
    const int nHD = H_ * D_;
    const int nTOT = BS_ * D_;
    const int nDD = D_ * D_;

    init_kernel<<<(nHD / 2 + 255) / 256, 256>>>(W1, W2);
    gates_kernel<<<NC_, 512>>>(x, wdec, bdec, wlr, blr, weta, beta);

    cvt_kernel<<<(nTOT / 2 + 255) / 256, 256>>>(x, xh, xl, nTOT / 2);
    cvt_kernel<<<(nDD / 2 + 255) / 256, 256>>>(Wk, Wkh, Wkl, nDD / 2);
    cvt_kernel<<<(nDD / 2 + 255) / 256, 256>>>(Wv, Wvh, Wvl, nDD / 2);
    cvt_kernel<<<(nDD / 2 + 255) / 256, 256>>>(Wq, Wqh, Wql, nDD / 2);
    cvt_f16_kernel<<<(nDD / 2 + 255) / 256, 256>>>(Wout, Wof, nDD / 2);

    run<0, false, false>(xh, xl, Wkh, Wkl, proj, nullptr, nullptr, nullptr, nullptr, nullptr,
                         BS_, D_, D_, 0);
    conv_chunk_kernel<<<(nTOT + 255) / 256, 256>>>(proj, ckw, ckb, kch, kcl, nullptr, nullptr);
    run<0, false, false>(xh, xl, Wvh, Wvl, proj, nullptr, nullptr, nullptr, nullptr, nullptr,
                         BS_, D_, D_, 0);
    conv_chunk_kernel<<<(nTOT + 255) / 256, 256>>>(proj, cvw, cvb, nullptr, nullptr, vc, nullptr);
    run<0, false, false>(xh, xl, Wqh, Wql, proj, nullptr, nullptr, nullptr, nullptr, nullptr,
                         BS_, D_, D_, 0);
    conv_chunk_kernel<<<(nTOT + 255) / 256, 256>>>(proj, cqw, cqb, nullptr, nullptr, nullptr, qf);

    cudaFuncSetAttribute(dual_tb_a1, cudaFuncAttributeMaxDynamicSharedMemorySize, GSMEM);
    cudaFuncSetAttribute(dual8_y_d2, cudaFuncAttributeMaxDynamicSharedMemorySize, GSMEM8);
    cudaFuncSetAttribute(mma_update_dual, cudaFuncAttributeMaxDynamicSharedMemorySize, GSMEM);

    // prologue: a1(0)+sd(0) with E1=W1; d2(0) with E2=W2
    run8<1, false, false>(kch, kcl, E1h, E1l, nullptr, a1h, a1l,
                          nullptr, sd, nullptr, R_, H_, D_, 0);
    run8<2, false, false>(a1h, a1l, E2h, E2l, nullptr, d2h, d2l,
                          vc, nullptr, nullptr, R_, D_, H_, 0);

    for (int c = 0; c < NC_; c++) {
        const size_t off  = (size_t)c * nRD;
        const size_t offn = (size_t)(c + 1) * nRD;
        const int yext = (c + 1 < NC_) ? 16 : 8;

        // d1(c) = (d2 E2_old) * sd    — 128 CTAs, 8-warp split-K, bf16x3
        run8<3, false, true>(d2h, d2l, E2h, E2l, nullptr, d1h, d1l,
                             sd, nullptr, nullptr, R_, H_, D_, 0);
        // fused updates: g2 -> E2 (hi/lo + f16) ; g1 -> E1 (hi/lo + f16)
        mma_update_dual<<<256, 128, GSMEM>>>(d2h, d2l, a1h, a1l, d1h, d1l,
                                             kch + off, kcl + off,
                                             W2, M2, Wd2, E2h, E2l, E2f,
                                             W1, M1, Wd1, E1h, E1l, E1f, c);
        // tb(c) fp16 1-pass + a1'(c+1) bf16x3
        dual_tb_a1<<<dim3(16, yext), 128, GSMEM>>>(
            qf + off, E1f, tbf,
            kch + offn, kcl + offn, E1h, E1l, a1h, a1l, sd);
        // y(c) fp16 1-pass K=1024 + d2'(c+1) bf16x3 K=1024
        dual8_y_d2<<<dim3(8, yext), 256, GSMEM8>>>(
            tbf, E2f, ych + off,
            a1h, a1l, E2h, E2l, vc + offn, d2h, d2l);
    }

    permute_y_kernel<<<(nTOT + 255) / 256, 256>>>();
    run_f16<0>(yf, Wof, out, nullptr, BS_, D_, D_);
}

// round 14
// speedup vs baseline: 1.0578x; 1.0578x over previous
#include <cuda_runtime.h>
#include <cuda_bf16.h>
#include <cuda_fp16.h>
#include <math.h>
#include <stdint.h>

// ---------------- problem dims ----------------
#define B_   8
#define S_   4096
#define D_   512
#define H_   1024
#define Kc_  4
#define CS_  64
#define NC_  64
#define BS_  (B_ * S_)
#define R_   512
#define ERR_CLIP  1.0f
#define GRAD_CLIP 1.0f
#define SCALE_    0.03125f

typedef __nv_bfloat16 bf16;
typedef __nv_bfloat162 bf162;
typedef __half hf;

// ---------------- device scratch ----------------
__device__ float g_proj[(size_t)BS_ * D_];
__device__ float g_vc  [(size_t)BS_ * D_];
__device__ float g_ych [(size_t)BS_ * D_];
__device__ float g_sd  [(size_t)R_ * H_];
__device__ float g_Wd1 [(size_t)H_ * D_];
__device__ float g_M1  [(size_t)H_ * D_];
__device__ float g_Wd2 [(size_t)D_ * H_];
__device__ float g_M2  [(size_t)D_ * H_];
__device__ float g_alpha[NC_];
__device__ float g_lrg [NC_];
__device__ float g_eta [NC_];
__device__ hf   g_xf [(size_t)BS_ * D_];
__device__ hf   g_yf [(size_t)BS_ * D_];
__device__ bf16 g_kch[(size_t)BS_ * D_];
__device__ bf16 g_kcl[(size_t)BS_ * D_];
__device__ bf16 g_qch[(size_t)BS_ * D_];
__device__ bf16 g_qcl[(size_t)BS_ * D_];
__device__ bf16 g_a1h[(size_t)R_ * H_];
__device__ bf16 g_a1l[(size_t)R_ * H_];
__device__ bf16 g_d2h[(size_t)R_ * D_];
__device__ bf16 g_d2l[(size_t)R_ * D_];
__device__ bf16 g_d1h[(size_t)R_ * H_];
__device__ bf16 g_d1l[(size_t)R_ * H_];
__device__ bf16 g_tbh[(size_t)R_ * H_];
__device__ bf16 g_tbl[(size_t)R_ * H_];
__device__ bf16 g_E1h[(size_t)H_ * D_];
__device__ bf16 g_E1l[(size_t)H_ * D_];
__device__ bf16 g_E2h[(size_t)D_ * H_];
__device__ bf16 g_E2l[(size_t)D_ * H_];
__device__ hf   g_Wkf[(size_t)D_ * D_];
__device__ hf   g_Wvf[(size_t)D_ * D_];
__device__ hf   g_Wqf[(size_t)D_ * D_];
__device__ hf   g_Wof[(size_t)D_ * D_];

// ---------------- helpers ----------------
__device__ __forceinline__ float sigm(float x) { return 1.0f / (1.0f + __expf(-x)); }

__device__ __forceinline__ uint32_t smem_u32(const void* p) {
    uint32_t a;
    asm("{ .reg .u64 t; cvta.to.shared.u64 t, %1; cvt.u32.u64 %0, t; }" : "=r"(a) : "l"(p));
    return a;
}
__device__ __forceinline__ void ldsm4(uint32_t* r, uint32_t a) {
    asm volatile("ldmatrix.sync.aligned.m8n8.x4.shared.b16 {%0,%1,%2,%3}, [%4];"
        : "=r"(r[0]), "=r"(r[1]), "=r"(r[2]), "=r"(r[3]) : "r"(a));
}
__device__ __forceinline__ void ldsm4t(uint32_t* r, uint32_t a) {
    asm volatile("ldmatrix.sync.aligned.m8n8.x4.trans.shared.b16 {%0,%1,%2,%3}, [%4];"
        : "=r"(r[0]), "=r"(r[1]), "=r"(r[2]), "=r"(r[3]) : "r"(a));
}
__device__ __forceinline__ void mma16816(float* c, const uint32_t* a, uint32_t b0, uint32_t b1) {
    asm volatile("mma.sync.aligned.m16n8k16.row.col.f32.bf16.bf16.f32 "
        "{%0,%1,%2,%3}, {%4,%5,%6,%7}, {%8,%9}, {%0,%1,%2,%3};"
        : "+f"(c[0]), "+f"(c[1]), "+f"(c[2]), "+f"(c[3])
        : "r"(a[0]), "r"(a[1]), "r"(a[2]), "r"(a[3]), "r"(b0), "r"(b1));
}
__device__ __forceinline__ void mma16816h(float* c, const uint32_t* a, uint32_t b0, uint32_t b1) {
    asm volatile("mma.sync.aligned.m16n8k16.row.col.f32.f16.f16.f32 "
        "{%0,%1,%2,%3}, {%4,%5,%6,%7}, {%8,%9}, {%0,%1,%2,%3};"
        : "+f"(c[0]), "+f"(c[1]), "+f"(c[2]), "+f"(c[3])
        : "r"(a[0]), "r"(a[1]), "r"(a[2]), "r"(a[3]), "r"(b0), "r"(b1));
}
__device__ __forceinline__ void cpa(uint32_t dst, const void* src) {
    asm volatile("cp.async.cg.shared.global [%0], [%1], 16;" :: "r"(dst), "l"(src));
}
#define CP_COMMIT() asm volatile("cp.async.commit_group;" ::: "memory")
#define CP_WAIT(n)  asm volatile("cp.async.wait_group %0;" :: "n"(n) : "memory")

__device__ __forceinline__ void wr_hl(bf16* Ch, bf16* Cl, size_t idx, float v0, float v1)
{
    bf162 h(__float2bfloat16_rn(v0), __float2bfloat16_rn(v1));
    bf162 l(__float2bfloat16_rn(v0 - __bfloat162float(h.x)),
            __float2bfloat16_rn(v1 - __bfloat162float(h.y)));
    *(bf162*)(Ch + idx) = h;
    *(bf162*)(Cl + idx) = l;
}

// ---------------- tile loader (128-thread cooperative, one 64x64 16-bit tile) --------
template <bool TR>
__device__ __forceinline__ void load_tile(uint32_t sbase, const bf16* __restrict__ g,
                                          int org, int ld, int k0, int t)
{
    const int row = t >> 1;
    const int cb = (t & 1) << 2;
    const bf16* src = TR ? (g + (size_t)(k0 + row) * ld + org + cb * 8)
                         : (g + (size_t)(org + row) * ld + k0 + cb * 8);
#pragma unroll
    for (int i = 0; i < 4; i++) {
        const int c = cb + i;
        cpa(sbase + row * 128 + ((c ^ (row & 7)) << 4), src + i * 8);
    }
}

__device__ __forceinline__ void load_chunk4(uint32_t db,
    const bf16* __restrict__ Ah, const bf16* __restrict__ Al,
    const bf16* __restrict__ Bh, const bf16* __restrict__ Bl,
    int m0, int n0, int ldA, int ldB, int k0, int tl, bool AT, bool BT)
{
    if (AT) { load_tile<true >(db, Ah, m0, ldA, k0, tl); load_tile<true >(db + 8192, Al, m0, ldA, k0, tl); }
    else    { load_tile<false>(db, Ah, m0, ldA, k0, tl); load_tile<false>(db + 8192, Al, m0, ldA, k0, tl); }
    if (BT) { load_tile<true >(db + 16384, Bh, n0, ldB, k0, tl); load_tile<true >(db + 24576, Bl, n0, ldB, k0, tl); }
    else    { load_tile<false>(db + 16384, Bh, n0, ldB, k0, tl); load_tile<false>(db + 24576, Bl, n0, ldB, k0, tl); }
}

// ---------------- fragment loads ----------------
template <bool AT, bool BT>
__device__ __forceinline__ void load_frags(uint32_t ab, int ko, int wm, int wn, int lane,
    uint32_t (&ah)[2][4], uint32_t (&al)[2][4], uint32_t (&bh)[2][4], uint32_t (&bl)[2][4])
{
#pragma unroll
    for (int i = 0; i < 2; i++) {
        const int mf = wm * 32 + i * 16;
        uint32_t off;
        if (!AT) {
            const int row = mf + (lane & 7) + ((lane & 8) ? 8 : 0);
            const int ck = (ko >> 3) + ((lane >> 4) & 1);
            off = row * 128 + ((ck ^ (row & 7)) << 4);
            ldsm4(ah[i], ab + off);
            ldsm4(al[i], ab + 8192 + off);
        } else {
            const int row = ko + (lane & 7) + ((lane & 16) ? 8 : 0);
            const int ck = (mf >> 3) + ((lane >> 3) & 1);
            off = row * 128 + ((ck ^ (row & 7)) << 4);
            ldsm4t(ah[i], ab + off);
            ldsm4t(al[i], ab + 8192 + off);
        }
    }
#pragma unroll
    for (int jp = 0; jp < 2; jp++) {
        const int nf = wn * 32 + jp * 16;
        uint32_t off;
        if (!BT) {
            const int row = nf + (lane & 7) + ((lane & 16) ? 8 : 0);
            const int ck = (ko >> 3) + ((lane >> 3) & 1);
            off = row * 128 + ((ck ^ (row & 7)) << 4);
            ldsm4(bh[jp], ab + 16384 + off);
            ldsm4(bl[jp], ab + 24576 + off);
        } else {
            const int row = ko + (lane & 7) + ((lane & 8) ? 8 : 0);
            const int ck = (nf >> 3) + ((lane >> 4) & 1);
            off = row * 128 + ((ck ^ (row & 7)) << 4);
            ldsm4t(bh[jp], ab + 16384 + off);
            ldsm4t(bl[jp], ab + 24576 + off);
        }
    }
}

// fp16 single-pass fragments (NT direct; A @ab, B @ab+8192)
__device__ __forceinline__ void load_frags_f16(uint32_t ab, int ko, int wm, int wn, int lane,
    uint32_t (&a)[2][4], uint32_t (&b)[2][4])
{
#pragma unroll
    for (int i = 0; i < 2; i++) {
        const int row = wm * 32 + i * 16 + (lane & 7) + ((lane & 8) ? 8 : 0);
        const int ck = (ko >> 3) + ((lane >> 4) & 1);
        ldsm4(a[i], ab + row * 128 + ((ck ^ (row & 7)) << 4));
    }
#pragma unroll
    for (int jp = 0; jp < 2; jp++) {
        const int row = wn * 32 + jp * 16 + (lane & 7) + ((lane & 16) ? 8 : 0);
        const int ck = (ko >> 3) + ((lane >> 3) & 1);
        ldsm4(b[jp], ab + 8192 + row * 128 + ((ck ^ (row & 7)) << 4));
    }
}

// ---------------- one K=64 chunk of MMAs, register-double-buffered ----------------
template <bool AT, bool BT>
__device__ __forceinline__ void mma_chunk(uint32_t ab, float acc[2][4][4],
                                          int wm, int wn, int lane)
{
    uint32_t ah[2][2][4], al[2][2][4], bh[2][2][4], bl[2][2][4];
    load_frags<AT, BT>(ab, 0, wm, wn, lane, ah[0], al[0], bh[0], bl[0]);
#pragma unroll
    for (int koi = 0; koi < 4; koi++) {
        const int cur = koi & 1;
        if (koi < 3)
            load_frags<AT, BT>(ab, (koi + 1) << 4, wm, wn, lane,
                               ah[cur ^ 1], al[cur ^ 1], bh[cur ^ 1], bl[cur ^ 1]);
#pragma unroll
        for (int i = 0; i < 2; i++)
#pragma unroll
            for (int j = 0; j < 4; j++) {
                const int jp = j >> 1, wv = (j & 1) << 1;
                mma16816(acc[i][j], ah[cur][i], bh[cur][jp][wv], bh[cur][jp][wv + 1]);
                mma16816(acc[i][j], ah[cur][i], bl[cur][jp][wv], bl[cur][jp][wv + 1]);
                mma16816(acc[i][j], al[cur][i], bh[cur][jp][wv], bh[cur][jp][wv + 1]);
            }
    }
}

__device__ __forceinline__ void mma_chunk_f16(uint32_t ab, float acc[2][4][4],
                                              int wm, int wn, int lane)
{
    uint32_t a[2][2][4], b[2][2][4];
    load_frags_f16(ab, 0, wm, wn, lane, a[0], b[0]);
#pragma unroll
    for (int koi = 0; koi < 4; koi++) {
        const int cur = koi & 1;
        if (koi < 3)
            load_frags_f16(ab, (koi + 1) << 4, wm, wn, lane, a[cur ^ 1], b[cur ^ 1]);
#pragma unroll
        for (int i = 0; i < 2; i++)
#pragma unroll
            for (int j = 0; j < 4; j++) {
                const int jp = j >> 1, wv = (j & 1) << 1;
                mma16816h(acc[i][j], a[cur][i], b[cur][jp][wv], b[cur][jp][wv + 1]);
            }
    }
}

// ---------------- 4-warp GEMM mainloops ----------------
template <bool AT, bool BT>
__device__ __forceinline__ void gemm_main(
    const bf16* __restrict__ Ah, const bf16* __restrict__ Al,
    const bf16* __restrict__ Bh, const bf16* __restrict__ Bl,
    int m0, int n0, int ldA, int ldB, int K,
    uint32_t sb, int t, int wm, int wn, int lane, float acc[2][4][4])
{
    const int nch = K >> 6;
    load_chunk4(sb, Ah, Al, Bh, Bl, m0, n0, ldA, ldB, 0, t, AT, BT);
    CP_COMMIT();
    for (int ch = 0; ch < nch; ch++) {
        if (ch + 1 < nch) {
            load_chunk4(sb + ((ch + 1) & 1) * 32768, Ah, Al, Bh, Bl,
                        m0, n0, ldA, ldB, (ch + 1) << 6, t, AT, BT);
            CP_COMMIT();
            CP_WAIT(1);
        } else {
            CP_WAIT(0);
        }
        __syncthreads();
        mma_chunk<AT, BT>(sb + (ch & 1) * 32768, acc, wm, wn, lane);
        __syncthreads();
    }
}

__device__ __forceinline__ void gemm_main_f16(
    const hf* __restrict__ A, const hf* __restrict__ B,
    int m0, int n0, int ldA, int ldB, int K,
    uint32_t sb, int t, int wm, int wn, int lane, float acc[2][4][4])
{
    const int nch = K >> 6;
    load_tile<false>(sb,        (const bf16*)A, m0, ldA, 0, t);
    load_tile<false>(sb + 8192, (const bf16*)B, n0, ldB, 0, t);
    CP_COMMIT();
    for (int ch = 0; ch < nch; ch++) {
        if (ch + 1 < nch) {
            const uint32_t nb = sb + ((ch + 1) & 1) * 16384;
            const int k0 = (ch + 1) << 6;
            load_tile<false>(nb,        (const bf16*)A, m0, ldA, k0, t);
            load_tile<false>(nb + 8192, (const bf16*)B, n0, ldB, k0, t);
            CP_COMMIT();
            CP_WAIT(1);
        } else {
            CP_WAIT(0);
        }
        __syncthreads();
        mma_chunk_f16(sb + (ch & 1) * 16384, acc, wm, wn, lane);
        __syncthreads();
    }
}

// ---------------- 8-warp GEMM mainloop: warp-group split-K ----------------
template <bool AT, bool BT>
__device__ __forceinline__ void gemm_main8(
    const bf16* __restrict__ Ah, const bf16* __restrict__ Al,
    const bf16* __restrict__ Bh, const bf16* __restrict__ Bl,
    int m0, int n0, int ldA, int ldB, int K,
    uint32_t sb, int t, int wg, int wm, int wn, int lane, float acc[2][4][4])
{
    const int npair = K >> 7;
    const int tl = t & 127;
    const int which = t >> 7;
    load_chunk4(sb + which * 32768, Ah, Al, Bh, Bl, m0, n0, ldA, ldB,
                which << 6, tl, AT, BT);
    CP_COMMIT();
    for (int p = 0; p < npair; p++) {
        if (p + 1 < npair) {
            load_chunk4(sb + ((p + 1) & 1) * 65536 + which * 32768, Ah, Al, Bh, Bl,
                        m0, n0, ldA, ldB, ((p + 1) << 7) + (which << 6), tl, AT, BT);
            CP_COMMIT();
            CP_WAIT(1);
        } else {
            CP_WAIT(0);
        }
        __syncthreads();
        mma_chunk<AT, BT>(sb + (p & 1) * 65536 + wg * 32768, acc, wm, wn, lane);
        __syncthreads();
    }
}

__device__ __forceinline__ void reduce8(float acc[2][4][4], float* red,
                                        int wg, int wi, int lane)
{
    if (wg == 1) {
#pragma unroll
        for (int i = 0; i < 2; i++)
#pragma unroll
            for (int j = 0; j < 4; j++) {
                const int r = i * 16 + (lane >> 2);
                const int cc = j * 8 + ((lane & 3) << 1);
                *(float2*)&red[wi * 1024 + r * 32 + cc] = make_float2(acc[i][j][0], acc[i][j][1]);
                *(float2*)&red[wi * 1024 + (r + 8) * 32 + cc] = make_float2(acc[i][j][2], acc[i][j][3]);
            }
    }
    __syncthreads();
    if (wg == 0) {
#pragma unroll
        for (int i = 0; i < 2; i++)
#pragma unroll
            for (int j = 0; j < 4; j++) {
                const int r = i * 16 + (lane >> 2);
                const int cc = j * 8 + ((lane & 3) << 1);
                const float2 v0 = *(const float2*)&red[wi * 1024 + r * 32 + cc];
                const float2 v1 = *(const float2*)&red[wi * 1024 + (r + 8) * 32 + cc];
                acc[i][j][0] += v0.x; acc[i][j][1] += v0.y;
                acc[i][j][2] += v1.x; acc[i][j][3] += v1.y;
            }
    }
}

// ---------------- epilogues ----------------
template <int EPI>
__device__ __forceinline__ void epi_store(const float acc[2][4][4],
    int m0, int n0, int N, int wm, int wn, int lane,
    float* __restrict__ C, bf16* __restrict__ Ch, bf16* __restrict__ Cl,
    const float* __restrict__ X1, float* __restrict__ U1, float* __restrict__ U2,
    float ga, float gl, float ge)
{
#pragma unroll
    for (int i = 0; i < 2; i++)
#pragma unroll
        for (int j = 0; j < 4; j++) {
            const float* a = acc[i][j];
            const int mr0 = m0 + wm * 32 + i * 16 + (lane >> 2);
            const int nc  = n0 + wn * 32 + j * 8 + ((lane & 3) << 1);
            const size_t i0 = (size_t)mr0 * N + nc;
            const size_t i1 = (size_t)(mr0 + 8) * N + nc;

            if (EPI == 0) {
                *(float2*)(C + i0) = make_float2(a[0], a[1]);
                *(float2*)(C + i1) = make_float2(a[2], a[3]);
            } else if (EPI == 1) {
                const float s0 = sigm(a[0]), s1 = sigm(a[1]);
                const float s2 = sigm(a[2]), s3 = sigm(a[3]);
                wr_hl(Ch, Cl, i0, a[0] * s0, a[1] * s1);
                wr_hl(Ch, Cl, i1, a[2] * s2, a[3] * s3);
                *(float2*)(U1 + i0) = make_float2(s0 * (1.f + a[0] * (1.f - s0)),
                                                  s1 * (1.f + a[1] * (1.f - s1)));
                *(float2*)(U1 + i1) = make_float2(s2 * (1.f + a[2] * (1.f - s2)),
                                                  s3 * (1.f + a[3] * (1.f - s3)));
            } else if (EPI == 2) {
                const float2 v0 = *(const float2*)(X1 + i0);
                const float2 v1 = *(const float2*)(X1 + i1);
                wr_hl(Ch, Cl, i0,
                      SCALE_ * fminf(fmaxf(a[0] - v0.x, -ERR_CLIP), ERR_CLIP),
                      SCALE_ * fminf(fmaxf(a[1] - v0.y, -ERR_CLIP), ERR_CLIP));
                wr_hl(Ch, Cl, i1,
                      SCALE_ * fminf(fmaxf(a[2] - v1.x, -ERR_CLIP), ERR_CLIP),
                      SCALE_ * fminf(fmaxf(a[3] - v1.y, -ERR_CLIP), ERR_CLIP));
            } else if (EPI == 3) {
                const float2 v0 = *(const float2*)(X1 + i0);
                const float2 v1 = *(const float2*)(X1 + i1);
                wr_hl(Ch, Cl, i0, a[0] * v0.x, a[1] * v0.y);
                wr_hl(Ch, Cl, i1, a[2] * v1.x, a[3] * v1.y);
            } else if (EPI == 4) {
                float2 mo0 = *(float2*)(U1 + i0), mo1 = *(float2*)(U1 + i1);
                float2 wd0 = *(float2*)(U2 + i0), wd1 = *(float2*)(U2 + i1);
                mo0.x = ge * mo0.x - gl * fminf(fmaxf(a[0], -GRAD_CLIP), GRAD_CLIP);
                mo0.y = ge * mo0.y - gl * fminf(fmaxf(a[1], -GRAD_CLIP), GRAD_CLIP);
                mo1.x = ge * mo1.x - gl * fminf(fmaxf(a[2], -GRAD_CLIP), GRAD_CLIP);
                mo1.y = ge * mo1.y - gl * fminf(fmaxf(a[3], -GRAD_CLIP), GRAD_CLIP);
                wd0.x = (1.f - ga) * wd0.x + mo0.x;
                wd0.y = (1.f - ga) * wd0.y + mo0.y;
                wd1.x = (1.f - ga) * wd1.x + mo1.x;
                wd1.y = (1.f - ga) * wd1.y + mo1.y;
                *(float2*)(U1 + i0) = mo0; *(float2*)(U1 + i1) = mo1;
                *(float2*)(U2 + i0) = wd0; *(float2*)(U2 + i1) = wd1;
                const float2 w0 = *(const float2*)(X1 + i0);
                const float2 w1 = *(const float2*)(X1 + i1);
                wr_hl(Ch, Cl, i0, w0.x + wd0.x, w0.y + wd0.y);
                wr_hl(Ch, Cl, i1, w1.x + wd1.x, w1.y + wd1.y);
            } else { // EPI 5
                wr_hl(Ch, Cl, i0, a[0] * sigm(a[0]), a[1] * sigm(a[1]));
                wr_hl(Ch, Cl, i1, a[2] * sigm(a[2]), a[3] * sigm(a[3]));
            }
        }
}

#define GSMEM   65536
#define GSMEM8  131072
#define GSMEMF  32768

// ---------------- 4-warp solo GEMM kernel (bf16x3) ----------------
template <int EPI, bool AT, bool BT>
__global__ void __launch_bounds__(128)
mma_gemm(const bf16* __restrict__ Ah, const bf16* __restrict__ Al,
         const bf16* __restrict__ Bh, const bf16* __restrict__ Bl,
         float* __restrict__ C, bf16* __restrict__ Ch, bf16* __restrict__ Cl,
         const float* __restrict__ X1, float* __restrict__ U1, float* __restrict__ U2,
         int M, int N, int K, int gate)
{
    extern __shared__ __align__(1024) char smem[];
    const int t = threadIdx.x, lane = t & 31, w = t >> 5;
    const int wm = w & 1, wn = w >> 1;
    const int m0 = blockIdx.y << 6, n0 = blockIdx.x << 6;
    const uint32_t sb = smem_u32(smem);
    float acc[2][4][4] = {};
    gemm_main<AT, BT>(Ah, Al, Bh, Bl, m0, n0, AT ? M : K, BT ? N : K, K,
                      sb, t, wm, wn, lane, acc);
    epi_store<EPI>(acc, m0, n0, N, wm, wn, lane, C, Ch, Cl, X1, U1, U2, 0.f, 0.f, 0.f);
}

// ---------------- 4-warp solo fp16 GEMM kernel (C = A*B^T, fp32 out) ----------------
__global__ void __launch_bounds__(128)
mma_gemm_f16k(const hf* __restrict__ A, const hf* __restrict__ B,
              float* __restrict__ C, int M, int N, int K)
{
    extern __shared__ __align__(1024) char smem[];
    const int t = threadIdx.x, lane = t & 31, w = t >> 5;
    const int wm = w & 1, wn = w >> 1;
    const int m0 = blockIdx.y << 6, n0 = blockIdx.x << 6;
    const uint32_t sb = smem_u32(smem);
    float acc[2][4][4] = {};
    gemm_main_f16(A, B, m0, n0, K, K, K, sb, t, wm, wn, lane, acc);
    epi_store<0>(acc, m0, n0, N, wm, wn, lane, C, nullptr, nullptr,
                 nullptr, nullptr, nullptr, 0.f, 0.f, 0.f);
}

// ---------------- 8-warp solo GEMM kernel (bf16x3) ----------------
template <int EPI, bool AT, bool BT>
__global__ void __launch_bounds__(256)
mma_gemm8(const bf16* __restrict__ Ah, const bf16* __restrict__ Al,
          const bf16* __restrict__ Bh, const bf16* __restrict__ Bl,
          float* __restrict__ C, bf16* __restrict__ Ch, bf16* __restrict__ Cl,
          const float* __restrict__ X1, float* __restrict__ U1, float* __restrict__ U2,
          int M, int N, int K, int gate)
{
    extern __shared__ __align__(1024) char smem[];
    const int t = threadIdx.x, lane = t & 31, w = t >> 5;
    const int wg = w >> 2, wi = w & 3;
    const int wm = wi & 1, wn = wi >> 1;
    const int m0 = blockIdx.y << 6, n0 = blockIdx.x << 6;
    const uint32_t sb = smem_u32(smem);
    float acc[2][4][4] = {};
    gemm_main8<AT, BT>(Ah, Al, Bh, Bl, m0, n0, AT ? M : K, BT ? N : K, K,
                       sb, t, wg, wm, wn, lane, acc);
    reduce8(acc, (float*)smem, wg, wi, lane);
    if (wg == 0)
        epi_store<EPI>(acc, m0, n0, N, wm, wn, lane, C, Ch, Cl, X1, U1, U2, 0.f, 0.f, 0.f);
}

// ---------------- 4-warp dual-segment GEMM (shared B, bf16x3) ----------------
template <int EPIa, int EPIb>
__global__ void __launch_bounds__(128)
mma_gemm_dual(const bf16* __restrict__ Aah, const bf16* __restrict__ Aal,
              const bf16* __restrict__ Abh, const bf16* __restrict__ Abl, int Ma,
              const bf16* __restrict__ Bh, const bf16* __restrict__ Bl,
              float* __restrict__ Ca, bf16* __restrict__ Cah, bf16* __restrict__ Cal,
              const float* __restrict__ X1a, float* __restrict__ U1a,
              float* __restrict__ Cb, bf16* __restrict__ Cbh, bf16* __restrict__ Cbl,
              const float* __restrict__ X1b, float* __restrict__ U1b,
              int N, int K)
{
    extern __shared__ __align__(1024) char smem[];
    const int t = threadIdx.x, lane = t & 31, w = t >> 5;
    const int wm = w & 1, wn = w >> 1;
    const int ya = Ma >> 6;
    const bool segb = (int)blockIdx.y >= ya;
    const bf16* Ah = segb ? Abh : Aah;
    const bf16* Al = segb ? Abl : Aal;
    const int m0 = (segb ? ((int)blockIdx.y - ya) : (int)blockIdx.y) << 6;
    const int n0 = blockIdx.x << 6;
    const uint32_t sb = smem_u32(smem);
    float acc[2][4][4] = {};
    gemm_main<false, false>(Ah, Al, Bh, Bl, m0, n0, K, K, K, sb, t, wm, wn, lane, acc);
    if (!segb)
        epi_store<EPIa>(acc, m0, n0, N, wm, wn, lane, Ca, Cah, Cal, X1a, U1a, nullptr,
                        0.f, 0.f, 0.f);
    else
        epi_store<EPIb>(acc, m0, n0, N, wm, wn, lane, Cb, Cbh, Cbl, X1b, U1b, nullptr,
                        0.f, 0.f, 0.f);
}

// ---------------- 8-warp dual-segment GEMM (bf16x3) ----------------
template <int EPIa, int EPIb>
__global__ void __launch_bounds__(256)
mma_gemm_dual8(const bf16* __restrict__ Aah, const bf16* __restrict__ Aal,
               const bf16* __restrict__ Abh, const bf16* __restrict__ Abl, int Ma,
               const bf16* __restrict__ Bh, const bf16* __restrict__ Bl,
               float* __restrict__ Ca, bf16* __restrict__ Cah, bf16* __restrict__ Cal,
               const float* __restrict__ X1a, float* __restrict__ U1a,
               float* __restrict__ Cb, bf16* __restrict__ Cbh, bf16* __restrict__ Cbl,
               const float* __restrict__ X1b, float* __restrict__ U1b,
               int N, int K)
{
    extern __shared__ __align__(1024) char smem[];
    const int t = threadIdx.x, lane = t & 31, w = t >> 5;
    const int wg = w >> 2, wi = w & 3;
    const int wm = wi & 1, wn = wi >> 1;
    const int ya = Ma >> 6;
    const bool segb = (int)blockIdx.y >= ya;
    const bf16* Ah = segb ? Abh : Aah;
    const bf16* Al = segb ? Abl : Aal;
    const int m0 = (segb ? ((int)blockIdx.y - ya) : (int)blockIdx.y) << 6;
    const int n0 = blockIdx.x << 6;
    const uint32_t sb = smem_u32(smem);
    float acc[2][4][4] = {};
    gemm_main8<false, false>(Ah, Al, Bh, Bl, m0, n0, K, K, K,
                             sb, t, wg, wm, wn, lane, acc);
    reduce8(acc, (float*)smem, wg, wi, lane);
    if (wg == 0) {
        if (!segb)
            epi_store<EPIa>(acc, m0, n0, N, wm, wn, lane, Ca, Cah, Cal, X1a, U1a, nullptr,
                            0.f, 0.f, 0.f);
        else
            epi_store<EPIb>(acc, m0, n0, N, wm, wn, lane, Cb, Cbh, Cbl, X1b, U1b, nullptr,
                            0.f, 0.f, 0.f);
    }
}

// ---------------- fused dual-update kernel (4-warp; 256 CTAs) ----------------
__global__ void __launch_bounds__(128)
mma_update_dual(const bf16* __restrict__ d2h, const bf16* __restrict__ d2l,
                const bf16* __restrict__ a1h, const bf16* __restrict__ a1l,
                const bf16* __restrict__ d1h, const bf16* __restrict__ d1l,
                const bf16* __restrict__ kchp, const bf16* __restrict__ kclp,
                const float* __restrict__ W2, float* __restrict__ M2,
                float* __restrict__ Wd2, bf16* __restrict__ E2h, bf16* __restrict__ E2l,
                const float* __restrict__ W1, float* __restrict__ M1,
                float* __restrict__ Wd1, bf16* __restrict__ E1h, bf16* __restrict__ E1l,
                int gate)
{
    extern __shared__ __align__(1024) char smem[];
    const int t = threadIdx.x, lane = t & 31, w = t >> 5;
    const int wm = w & 1, wn = w >> 1;
    const int bid = blockIdx.x;
    const bool segb = bid >= 128;
    const uint32_t sb = smem_u32(smem);
    const float ga = g_alpha[gate], gl = g_lrg[gate], ge = g_eta[gate];
    float acc[2][4][4] = {};
    if (!segb) {
        const int n0 = (bid & 15) << 6, m0 = (bid >> 4) << 6;
        gemm_main<true, true>(d2h, d2l, a1h, a1l, m0, n0, D_, H_, R_,
                              sb, t, wm, wn, lane, acc);
        epi_store<4>(acc, m0, n0, H_, wm, wn, lane, nullptr, E2h, E2l, W2, M2, Wd2,
                     ga, gl, ge);
    } else {
        const int r = bid - 128;
        const int n0 = (r & 7) << 6, m0 = (r >> 3) << 6;
        gemm_main<true, true>(d1h, d1l, kchp, kclp, m0, n0, H_, D_, R_,
                              sb, t, wm, wn, lane, acc);
        epi_store<4>(acc, m0, n0, D_, wm, wn, lane, nullptr, E1h, E1l, W1, M1, Wd1,
                     ga, gl, ge);
    }
}

template <int EPI, bool AT, bool BT>
static void run(const bf16* Ah, const bf16* Al, const bf16* Bh, const bf16* Bl,
                float* C, bf16* Ch, bf16* Cl,
                const float* X1, float* U1, float* U2, int M, int N, int K, int gate)
{
    cudaFuncSetAttribute(mma_gemm<EPI, AT, BT>,
                         cudaFuncAttributeMaxDynamicSharedMemorySize, GSMEM);
    dim3 grid(N >> 6, M >> 6);
    mma_gemm<EPI, AT, BT><<<grid, 128, GSMEM>>>(Ah, Al, Bh, Bl, C, Ch, Cl, X1, U1, U2,
                                                M, N, K, gate);
}

template <int EPI, bool AT, bool BT>
static void run8(const bf16* Ah, const bf16* Al, const bf16* Bh, const bf16* Bl,
                 float* C, bf16* Ch, bf16* Cl,
                 const float* X1, float* U1, float* U2, int M, int N, int K, int gate)
{
    cudaFuncSetAttribute(mma_gemm8<EPI, AT, BT>,
                         cudaFuncAttributeMaxDynamicSharedMemorySize, GSMEM8);
    dim3 grid(N >> 6, M >> 6);
    mma_gemm8<EPI, AT, BT><<<grid, 256, GSMEM8>>>(Ah, Al, Bh, Bl, C, Ch, Cl, X1, U1, U2,
                                                  M, N, K, gate);
}

static void run_f16(const hf* A, const hf* B, float* C, int M, int N, int K)
{
    cudaFuncSetAttribute(mma_gemm_f16k,
                         cudaFuncAttributeMaxDynamicSharedMemorySize, GSMEMF);
    dim3 grid(N >> 6, M >> 6);
    mma_gemm_f16k<<<grid, 128, GSMEMF>>>(A, B, C, M, N, K);
}

// ---------------- misc kernels ----------------
__global__ void init_kernel(const float* __restrict__ W1, const float* __restrict__ W2)
{
    const size_t i = ((size_t)blockIdx.x * blockDim.x + threadIdx.x) * 2;
    if (i >= (size_t)H_ * D_) return;
    *(float2*)(g_Wd1 + i) = make_float2(0.f, 0.f);
    *(float2*)(g_M1  + i) = make_float2(0.f, 0.f);
    *(float2*)(g_Wd2 + i) = make_float2(0.f, 0.f);
    *(float2*)(g_M2  + i) = make_float2(0.f, 0.f);
    const float2 w1 = *(const float2*)(W1 + i);
    const float2 w2 = *(const float2*)(W2 + i);
    wr_hl(g_E1h, g_E1l, i, w1.x, w1.y);
    wr_hl(g_E2h, g_E2l, i, w2.x, w2.y);
}

__global__ void cvt_f16_kernel(const float* __restrict__ s, hf* __restrict__ d, int n2)
{
    const int i = blockIdx.x * blockDim.x + threadIdx.x;
    if (i >= n2) return;
    const float2 v = ((const float2*)s)[i];
    *(__half2*)(d + (size_t)i * 2) = __floats2half2_rn(v.x, v.y);
}

// causal depthwise conv -> chunk-major [NC][R][D]; out: bf16 hi/lo OR fp32
__global__ void conv_chunk_kernel(const float* __restrict__ in, const float* __restrict__ w,
                                  const float* __restrict__ bias,
                                  bf16* __restrict__ oh, bf16* __restrict__ ol,
                                  float* __restrict__ of)
{
    const size_t i = (size_t)blockIdx.x * blockDim.x + threadIdx.x;
    if (i >= (size_t)BS_ * D_) return;
    const int d = (int)(i & (D_ - 1));
    const size_t bs = i >> 9;
    const int s = (int)(bs & (S_ - 1));
    const int b = (int)(bs >> 12);
    float acc = bias[d];
#pragma unroll
    for (int j = 0; j < Kc_; j++) {
        const int sp = s - (Kc_ - 1) + j;
        if (sp >= 0)
            acc = fmaf(w[d * Kc_ + j], in[((size_t)b * S_ + sp) * D_ + d], acc);
    }
    const int c  = s >> 6;
    const int cs = s & 63;
    const size_t o = (((size_t)c * R_ + (b * CS_ + cs)) << 9) + d;
    if (of) {
        of[o] = acc;
    } else {
        const bf16 hv = __float2bfloat16_rn(acc);
        oh[o] = hv;
        ol[o] = __float2bfloat16_rn(acc - __bfloat162float(hv));
    }
}

__global__ void gates_kernel(const float* __restrict__ x,
                             const float* __restrict__ wd, const float* __restrict__ bd,
                             const float* __restrict__ wl, const float* __restrict__ bl,
                             const float* __restrict__ we, const float* __restrict__ be)
{
    const int c = blockIdx.x;
    const int t = threadIdx.x;
    const int b  = t >> 6;
    const int cs = t & 63;
    const float4* xr = (const float4*)(x + (((size_t)b * S_ + (size_t)c * CS_ + cs) << 9));
    const float4* w0 = (const float4*)wd;
    const float4* w1 = (const float4*)wl;
    const float4* w2 = (const float4*)we;
    float s0 = 0.f, s1 = 0.f, s2 = 0.f;
#pragma unroll 4
    for (int d = 0; d < D_ / 4; d++) {
        const float4 xv = xr[d];
        const float4 a0 = w0[d], a1 = w1[d], a2 = w2[d];
        s0 += xv.x * a0.x + xv.y * a0.y + xv.z * a0.z + xv.w * a0.w;
        s1 += xv.x * a1.x + xv.y * a1.y + xv.z * a1.z + xv.w * a1.w;
        s2 += xv.x * a2.x + xv.y * a2.y + xv.z * a2.z + xv.w * a2.w;
    }
    s0 = sigm(s0 + bd[0]);
    s1 = sigm(s1 + bl[0]);
    s2 = sigm(s2 + be[0]);

    __shared__ float r0[512], r1[512], r2[512];
    r0[t] = s0; r1[t] = s1; r2[t] = s2;
    __syncthreads();
    for (int off = 256; off > 0; off >>= 1) {
        if (t < off) { r0[t] += r0[t + off]; r1[t] += r1[t + off]; r2[t] += r2[t + off]; }
        __syncthreads();
    }
    if (t == 0) {
        g_alpha[c] = r0[0] * (1.0f / 512.0f);
        g_lrg[c]   = r1[0] * (1.0f / 512.0f);
        g_eta[c]   = r2[0] * (1.0f / 512.0f);
    }
}

// chunk-major ych -> flat [B,S,D] as fp16
__global__ void permute_y_kernel()
{
    const size_t i = (size_t)blockIdx.x * blockDim.x + threadIdx.x;
    if (i >= (size_t)BS_ * D_) return;
    const int d = (int)(i & (D_ - 1));
    const size_t rw = i >> 9;
    const int s = (int)(rw & (S_ - 1));
    const int b = (int)(rw >> 12);
    const int c  = s >> 6;
    const int cs = s & 63;
    g_yf[i] = __float2half_rn(g_ych[(((size_t)c * R_ + (b * CS_ + cs)) << 9) + d]);
}

// ---------------- entry point ----------------
extern "C" void kernel_launch(void* const* d_in, const int* in_sizes, int n_in,
                              void* d_out, int out_size)
{
    (void)in_sizes; (void)n_in; (void)out_size;
    const float* x    = (const float*)d_in[0];
    const float* Wk   = (const float*)d_in[1];
    const float* Wv   = (const float*)d_in[2];
    const float* Wq   = (const float*)d_in[3];
    const float* Wout = (const float*)d_in[4];
    const float* ckw  = (const float*)d_in[5];
    const float* ckb  = (const float*)d_in[6];
    const float* cvw  = (const float*)d_in[7];
    const float* cvb  = (const float*)d_in[8];
    const float* cqw  = (const float*)d_in[9];
    const float* cqb  = (const float*)d_in[10];
    const float* wdec = (const float*)d_in[11];
    const float* bdec = (const float*)d_in[12];
    const float* wlr  = (const float*)d_in[13];
    const float* blr  = (const float*)d_in[14];
    const float* weta = (const float*)d_in[15];
    const float* beta = (const float*)d_in[16];
    const float* W1   = (const float*)d_in[17];
    const float* W2   = (const float*)d_in[18];
    float* out = (float*)d_out;

    float *proj, *vc, *ych, *sd, *Wd1, *M1, *Wd2, *M2;
    bf16 *kch, *kcl, *qch, *qcl, *a1h, *a1l, *d2h, *d2l, *d1h, *d1l, *tbh, *tbl;
    bf16 *E1h, *E1l, *E2h, *E2l;
    hf *xf, *yf, *Wkf, *Wvf, *Wqf, *Wof;
    cudaGetSymbolAddress((void**)&proj, g_proj);
    cudaGetSymbolAddress((void**)&vc,   g_vc);
    cudaGetSymbolAddress((void**)&ych,  g_ych);
    cudaGetSymbolAddress((void**)&sd,   g_sd);
    cudaGetSymbolAddress((void**)&Wd1,  g_Wd1);
    cudaGetSymbolAddress((void**)&M1,   g_M1);
    cudaGetSymbolAddress((void**)&Wd2,  g_Wd2);
    cudaGetSymbolAddress((void**)&M2,   g_M2);
    cudaGetSymbolAddress((void**)&xf,  g_xf);  cudaGetSymbolAddress((void**)&yf,  g_yf);
    cudaGetSymbolAddress((void**)&kch, g_kch); cudaGetSymbolAddress((void**)&kcl, g_kcl);
    cudaGetSymbolAddress((void**)&qch, g_qch); cudaGetSymbolAddress((void**)&qcl, g_qcl);
    cudaGetSymbolAddress((void**)&a1h, g_a1h); cudaGetSymbolAddress((void**)&a1l, g_a1l);
    cudaGetSymbolAddress((void**)&d2h, g_d2h); cudaGetSymbolAddress((void**)&d2l, g_d2l);
    cudaGetSymbolAddress((void**)&d1h, g_d1h); cudaGetSymbolAddress((void**)&d1l, g_d1l);
    cudaGetSymbolAddress((void**)&tbh, g_tbh); cudaGetSymbolAddress((void**)&tbl, g_tbl);
    cudaGetSymbolAddress((void**)&E1h, g_E1h); cudaGetSymbolAddress((void**)&E1l, g_E1l);
    cudaGetSymbolAddress((void**)&E2h, g_E2h); cudaGetSymbolAddress((void**)&E2l, g_E2l);
    cudaGetSymbolAddress((void**)&Wkf, g_Wkf); cudaGetSymbolAddress((void**)&Wvf, g_Wvf);
    cudaGetSymbolAddress((void**)&Wqf, g_Wqf); cudaGetSymbolAddress((void**)&Wof, g_Wof);

    const int nRD = R_ * D_;
    const int nHD = H_ * D_;
    const int nTOT = BS_ * D_;
    const int nDD = D_ * D_;

    init_kernel<<<(nHD / 2 + 255) / 256, 256>>>(W1, W2);
    gates_kernel<<<NC_, 512>>>(x, wdec, bdec, wlr, blr, weta, beta);

    // preconvert inputs/weights to fp16 for the 4 big boundary GEMMs
    cvt_f16_kernel<<<(nTOT / 2 + 255) / 256, 256>>>(x, xf, nTOT / 2);
    cvt_f16_kernel<<<(nDD / 2 + 255) / 256, 256>>>(Wk, Wkf, nDD / 2);
    cvt_f16_kernel<<<(nDD / 2 + 255) / 256, 256>>>(Wv, Wvf, nDD / 2);
    cvt_f16_kernel<<<(nDD / 2 + 255) / 256, 256>>>(Wq, Wqf, nDD / 2);
    cvt_f16_kernel<<<(nDD / 2 + 255) / 256, 256>>>(Wout, Wof, nDD / 2);

    // projections (fp16 1-pass) + causal conv -> chunk-major operands
    run_f16(xf, Wkf, proj, BS_, D_, D_);
    conv_chunk_kernel<<<(nTOT + 255) / 256, 256>>>(proj, ckw, ckb, kch, kcl, nullptr);
    run_f16(xf, Wvf, proj, BS_, D_, D_);
    conv_chunk_kernel<<<(nTOT + 255) / 256, 256>>>(proj, cvw, cvb, nullptr, nullptr, vc);
    run_f16(xf, Wqf, proj, BS_, D_, D_);
    conv_chunk_kernel<<<(nTOT + 255) / 256, 256>>>(proj, cqw, cqb, qch, qcl, nullptr);

    cudaFuncSetAttribute(mma_gemm_dual<5, 1>,
                         cudaFuncAttributeMaxDynamicSharedMemorySize, GSMEM);
    cudaFuncSetAttribute(mma_gemm_dual8<0, 2>,
                         cudaFuncAttributeMaxDynamicSharedMemorySize, GSMEM8);
    cudaFuncSetAttribute(mma_update_dual,
                         cudaFuncAttributeMaxDynamicSharedMemorySize, GSMEM);

    // prologue: a1(0)+sd(0) with E1=W1; d2(0) with E2=W2  (bf16x3, 8-warp)
    run8<1, false, false>(kch, kcl, E1h, E1l, nullptr, a1h, a1l,
                          nullptr, sd, nullptr, R_, H_, D_, 0);
    run8<2, false, false>(a1h, a1l, E2h, E2l, nullptr, d2h, d2l,
                          vc, nullptr, nullptr, R_, D_, H_, 0);

    for (int c = 0; c < NC_; c++) {
        const size_t off  = (size_t)c * nRD;
        const size_t offn = (size_t)(c + 1) * nRD;

        // d1(c) = (d2 E2_old) * sd    — 128 CTAs, 8-warp split-K
        run8<3, false, true>(d2h, d2l, E2h, E2l, nullptr, d1h, d1l,
                             sd, nullptr, nullptr, R_, H_, D_, 0);
        // fused updates: g2 -> E2 new ; g1 -> E1 new (256 CTAs, 4-warp)
        mma_update_dual<<<256, 128, GSMEM>>>(d2h, d2l, a1h, a1l, d1h, d1l,
                                             kch + off, kcl + off,
                                             W2, M2, Wd2, E2h, E2l,
                                             W1, M1, Wd1, E1h, E1l, c);
        if (c + 1 < NC_) {
            // fused: tb(c) = silu(Qc E1^T) + a1,sd(c+1) (256 CTAs, 4-warp)
            mma_gemm_dual<5, 1><<<dim3(H_ >> 6, 16), 128, GSMEM>>>(
                qch + off, qcl + off, kch + offn, kcl + offn, R_,
                E1h, E1l,
                nullptr, tbh, tbl, nullptr, nullptr,
                nullptr, a1h, a1l, nullptr, sd,
                H_, D_);
            // fused: y(c) = tb E2^T + d2(c+1) (128 CTAs, K=1024, 8-warp)
            mma_gemm_dual8<0, 2><<<dim3(D_ >> 6, 16), 256, GSMEM8>>>(
                tbh, tbl, a1h, a1l, R_,
                E2h, E2l,
                ych + off, nullptr, nullptr, nullptr, nullptr,
                nullptr, d2h, d2l, vc + offn, nullptr,
                D_, H_);
        } else {
            run8<5, false, false>(qch + off, qcl + off, E1h, E1l, nullptr, tbh, tbl,
                                  nullptr, nullptr, nullptr, R_, H_, D_, 0);
            run8<0, false, false>(tbh, tbl, E2h, E2l, ych + off, nullptr, nullptr,
                                  nullptr, nullptr, nullptr, R_, D_, H_, 0);
        }
    }

    permute_y_kernel<<<(nTOT + 255) / 256, 256>>>();
    run_f16(yf, Wof, out, BS_, D_, D_);
}

// round 15
// speedup vs baseline: 1.0859x; 1.0266x over previous
#include <cuda_runtime.h>
#include <cuda_bf16.h>
#include <cuda_fp16.h>
#include <math.h>
#include <stdint.h>

// ---------------- problem dims ----------------
#define B_   8
#define S_   4096
#define D_   512
#define H_   1024
#define Kc_  4
#define CS_  64
#define NC_  64
#define BS_  (B_ * S_)
#define R_   512
#define ERR_CLIP  1.0f
#define GRAD_CLIP 1.0f
#define SCALE_    0.03125f

typedef __nv_bfloat16 bf16;
typedef __nv_bfloat162 bf162;
typedef __half hf;

// ---------------- device scratch ----------------
__device__ float g_pk  [(size_t)BS_ * D_];
__device__ float g_pv  [(size_t)BS_ * D_];
__device__ float g_pq  [(size_t)BS_ * D_];
__device__ float g_vc  [(size_t)BS_ * D_];
__device__ float g_sd  [(size_t)R_ * H_];
__device__ float g_Wd1 [(size_t)H_ * D_];
__device__ float g_M1  [(size_t)H_ * D_];
__device__ float g_Wd2 [(size_t)D_ * H_];
__device__ float g_M2  [(size_t)D_ * H_];
__device__ float g_alpha[NC_];
__device__ float g_lrg [NC_];
__device__ float g_eta [NC_];
__device__ hf   g_xf [(size_t)BS_ * D_];
__device__ hf   g_yf [(size_t)BS_ * D_];
__device__ bf16 g_kch[(size_t)BS_ * D_];
__device__ bf16 g_kcl[(size_t)BS_ * D_];
__device__ bf16 g_qch[(size_t)BS_ * D_];
__device__ bf16 g_qcl[(size_t)BS_ * D_];
__device__ bf16 g_a1h[(size_t)R_ * H_];
__device__ bf16 g_a1l[(size_t)R_ * H_];
__device__ bf16 g_d2h[(size_t)R_ * D_];
__device__ bf16 g_d2l[(size_t)R_ * D_];
__device__ bf16 g_d1h[(size_t)R_ * H_];
__device__ bf16 g_d1l[(size_t)R_ * H_];
__device__ bf16 g_tbh[(size_t)R_ * H_];
__device__ bf16 g_tbl[(size_t)R_ * H_];
__device__ bf16 g_E1h[(size_t)H_ * D_];
__device__ bf16 g_E1l[(size_t)H_ * D_];
__device__ bf16 g_E2h[(size_t)D_ * H_];
__device__ bf16 g_E2l[(size_t)D_ * H_];
__device__ hf   g_Wkf[(size_t)D_ * D_];
__device__ hf   g_Wvf[(size_t)D_ * D_];
__device__ hf   g_Wqf[(size_t)D_ * D_];
__device__ hf   g_Wof[(size_t)D_ * D_];

// ---------------- helpers ----------------
__device__ __forceinline__ float sigm(float x) { return 1.0f / (1.0f + __expf(-x)); }

__device__ __forceinline__ uint32_t smem_u32(const void* p) {
    uint32_t a;
    asm("{ .reg .u64 t; cvta.to.shared.u64 t, %1; cvt.u32.u64 %0, t; }" : "=r"(a) : "l"(p));
    return a;
}
__device__ __forceinline__ void ldsm4(uint32_t* r, uint32_t a) {
    asm volatile("ldmatrix.sync.aligned.m8n8.x4.shared.b16 {%0,%1,%2,%3}, [%4];"
        : "=r"(r[0]), "=r"(r[1]), "=r"(r[2]), "=r"(r[3]) : "r"(a));
}
__device__ __forceinline__ void ldsm4t(uint32_t* r, uint32_t a) {
    asm volatile("ldmatrix.sync.aligned.m8n8.x4.trans.shared.b16 {%0,%1,%2,%3}, [%4];"
        : "=r"(r[0]), "=r"(r[1]), "=r"(r[2]), "=r"(r[3]) : "r"(a));
}
__device__ __forceinline__ void mma16816(float* c, const uint32_t* a, uint32_t b0, uint32_t b1) {
    asm volatile("mma.sync.aligned.m16n8k16.row.col.f32.bf16.bf16.f32 "
        "{%0,%1,%2,%3}, {%4,%5,%6,%7}, {%8,%9}, {%0,%1,%2,%3};"
        : "+f"(c[0]), "+f"(c[1]), "+f"(c[2]), "+f"(c[3])
        : "r"(a[0]), "r"(a[1]), "r"(a[2]), "r"(a[3]), "r"(b0), "r"(b1));
}
__device__ __forceinline__ void mma16816h(float* c, const uint32_t* a, uint32_t b0, uint32_t b1) {
    asm volatile("mma.sync.aligned.m16n8k16.row.col.f32.f16.f16.f32 "
        "{%0,%1,%2,%3}, {%4,%5,%6,%7}, {%8,%9}, {%0,%1,%2,%3};"
        : "+f"(c[0]), "+f"(c[1]), "+f"(c[2]), "+f"(c[3])
        : "r"(a[0]), "r"(a[1]), "r"(a[2]), "r"(a[3]), "r"(b0), "r"(b1));
}
__device__ __forceinline__ void cpa(uint32_t dst, const void* src) {
    asm volatile("cp.async.cg.shared.global [%0], [%1], 16;" :: "r"(dst), "l"(src));
}
#define CP_COMMIT() asm volatile("cp.async.commit_group;" ::: "memory")
#define CP_WAIT(n)  asm volatile("cp.async.wait_group %0;" :: "n"(n) : "memory")

__device__ __forceinline__ void wr_hl(bf16* Ch, bf16* Cl, size_t idx, float v0, float v1)
{
    bf162 h(__float2bfloat16_rn(v0), __float2bfloat16_rn(v1));
    bf162 l(__float2bfloat16_rn(v0 - __bfloat162float(h.x)),
            __float2bfloat16_rn(v1 - __bfloat162float(h.y)));
    *(bf162*)(Ch + idx) = h;
    *(bf162*)(Cl + idx) = l;
}

// ---------------- tile loader (128-thread cooperative, one 64x64 16-bit tile) --------
template <bool TR>
__device__ __forceinline__ void load_tile(uint32_t sbase, const bf16* __restrict__ g,
                                          int org, int ld, int k0, int t)
{
    const int row = t >> 1;
    const int cb = (t & 1) << 2;
    const bf16* src = TR ? (g + (size_t)(k0 + row) * ld + org + cb * 8)
                         : (g + (size_t)(org + row) * ld + k0 + cb * 8);
#pragma unroll
    for (int i = 0; i < 4; i++) {
        const int c = cb + i;
        cpa(sbase + row * 128 + ((c ^ (row & 7)) << 4), src + i * 8);
    }
}

__device__ __forceinline__ void load_chunk4(uint32_t db,
    const bf16* __restrict__ Ah, const bf16* __restrict__ Al,
    const bf16* __restrict__ Bh, const bf16* __restrict__ Bl,
    int m0, int n0, int ldA, int ldB, int k0, int tl, bool AT, bool BT)
{
    if (AT) { load_tile<true >(db, Ah, m0, ldA, k0, tl); load_tile<true >(db + 8192, Al, m0, ldA, k0, tl); }
    else    { load_tile<false>(db, Ah, m0, ldA, k0, tl); load_tile<false>(db + 8192, Al, m0, ldA, k0, tl); }
    if (BT) { load_tile<true >(db + 16384, Bh, n0, ldB, k0, tl); load_tile<true >(db + 24576, Bl, n0, ldB, k0, tl); }
    else    { load_tile<false>(db + 16384, Bh, n0, ldB, k0, tl); load_tile<false>(db + 24576, Bl, n0, ldB, k0, tl); }
}

// ---------------- fragment loads ----------------
template <bool AT, bool BT>
__device__ __forceinline__ void load_frags(uint32_t ab, int ko, int wm, int wn, int lane,
    uint32_t (&ah)[2][4], uint32_t (&al)[2][4], uint32_t (&bh)[2][4], uint32_t (&bl)[2][4])
{
#pragma unroll
    for (int i = 0; i < 2; i++) {
        const int mf = wm * 32 + i * 16;
        uint32_t off;
        if (!AT) {
            const int row = mf + (lane & 7) + ((lane & 8) ? 8 : 0);
            const int ck = (ko >> 3) + ((lane >> 4) & 1);
            off = row * 128 + ((ck ^ (row & 7)) << 4);
            ldsm4(ah[i], ab + off);
            ldsm4(al[i], ab + 8192 + off);
        } else {
            const int row = ko + (lane & 7) + ((lane & 16) ? 8 : 0);
            const int ck = (mf >> 3) + ((lane >> 3) & 1);
            off = row * 128 + ((ck ^ (row & 7)) << 4);
            ldsm4t(ah[i], ab + off);
            ldsm4t(al[i], ab + 8192 + off);
        }
    }
#pragma unroll
    for (int jp = 0; jp < 2; jp++) {
        const int nf = wn * 32 + jp * 16;
        uint32_t off;
        if (!BT) {
            const int row = nf + (lane & 7) + ((lane & 16) ? 8 : 0);
            const int ck = (ko >> 3) + ((lane >> 3) & 1);
            off = row * 128 + ((ck ^ (row & 7)) << 4);
            ldsm4(bh[jp], ab + 16384 + off);
            ldsm4(bl[jp], ab + 24576 + off);
        } else {
            const int row = ko + (lane & 7) + ((lane & 8) ? 8 : 0);
            const int ck = (nf >> 3) + ((lane >> 4) & 1);
            off = row * 128 + ((ck ^ (row & 7)) << 4);
            ldsm4t(bh[jp], ab + 16384 + off);
            ldsm4t(bl[jp], ab + 24576 + off);
        }
    }
}

// fp16 single-pass fragments (NT direct; A @ab, B @ab+8192)
__device__ __forceinline__ void load_frags_f16(uint32_t ab, int ko, int wm, int wn, int lane,
    uint32_t (&a)[2][4], uint32_t (&b)[2][4])
{
#pragma unroll
    for (int i = 0; i < 2; i++) {
        const int row = wm * 32 + i * 16 + (lane & 7) + ((lane & 8) ? 8 : 0);
        const int ck = (ko >> 3) + ((lane >> 4) & 1);
        ldsm4(a[i], ab + row * 128 + ((ck ^ (row & 7)) << 4));
    }
#pragma unroll
    for (int jp = 0; jp < 2; jp++) {
        const int row = wn * 32 + jp * 16 + (lane & 7) + ((lane & 16) ? 8 : 0);
        const int ck = (ko >> 3) + ((lane >> 3) & 1);
        ldsm4(b[jp], ab + 8192 + row * 128 + ((ck ^ (row & 7)) << 4));
    }
}

// ---------------- one K=64 chunk of MMAs, register-double-buffered ----------------
template <bool AT, bool BT>
__device__ __forceinline__ void mma_chunk(uint32_t ab, float acc[2][4][4],
                                          int wm, int wn, int lane)
{
    uint32_t ah[2][2][4], al[2][2][4], bh[2][2][4], bl[2][2][4];
    load_frags<AT, BT>(ab, 0, wm, wn, lane, ah[0], al[0], bh[0], bl[0]);
#pragma unroll
    for (int koi = 0; koi < 4; koi++) {
        const int cur = koi & 1;
        if (koi < 3)
            load_frags<AT, BT>(ab, (koi + 1) << 4, wm, wn, lane,
                               ah[cur ^ 1], al[cur ^ 1], bh[cur ^ 1], bl[cur ^ 1]);
#pragma unroll
        for (int i = 0; i < 2; i++)
#pragma unroll
            for (int j = 0; j < 4; j++) {
                const int jp = j >> 1, wv = (j & 1) << 1;
                mma16816(acc[i][j], ah[cur][i], bh[cur][jp][wv], bh[cur][jp][wv + 1]);
                mma16816(acc[i][j], ah[cur][i], bl[cur][jp][wv], bl[cur][jp][wv + 1]);
                mma16816(acc[i][j], al[cur][i], bh[cur][jp][wv], bh[cur][jp][wv + 1]);
            }
    }
}

__device__ __forceinline__ void mma_chunk_f16(uint32_t ab, float acc[2][4][4],
                                              int wm, int wn, int lane)
{
    uint32_t a[2][2][4], b[2][2][4];
    load_frags_f16(ab, 0, wm, wn, lane, a[0], b[0]);
#pragma unroll
    for (int koi = 0; koi < 4; koi++) {
        const int cur = koi & 1;
        if (koi < 3)
            load_frags_f16(ab, (koi + 1) << 4, wm, wn, lane, a[cur ^ 1], b[cur ^ 1]);
#pragma unroll
        for (int i = 0; i < 2; i++)
#pragma unroll
            for (int j = 0; j < 4; j++) {
                const int jp = j >> 1, wv = (j & 1) << 1;
                mma16816h(acc[i][j], a[cur][i], b[cur][jp][wv], b[cur][jp][wv + 1]);
            }
    }
}

// ---------------- 4-warp GEMM mainloops ----------------
template <bool AT, bool BT>
__device__ __forceinline__ void gemm_main(
    const bf16* __restrict__ Ah, const bf16* __restrict__ Al,
    const bf16* __restrict__ Bh, const bf16* __restrict__ Bl,
    int m0, int n0, int ldA, int ldB, int K,
    uint32_t sb, int t, int wm, int wn, int lane, float acc[2][4][4])
{
    const int nch = K >> 6;
    load_chunk4(sb, Ah, Al, Bh, Bl, m0, n0, ldA, ldB, 0, t, AT, BT);
    CP_COMMIT();
    for (int ch = 0; ch < nch; ch++) {
        if (ch + 1 < nch) {
            load_chunk4(sb + ((ch + 1) & 1) * 32768, Ah, Al, Bh, Bl,
                        m0, n0, ldA, ldB, (ch + 1) << 6, t, AT, BT);
            CP_COMMIT();
            CP_WAIT(1);
        } else {
            CP_WAIT(0);
        }
        __syncthreads();
        mma_chunk<AT, BT>(sb + (ch & 1) * 32768, acc, wm, wn, lane);
        __syncthreads();
    }
}

__device__ __forceinline__ void gemm_main_f16(
    const hf* __restrict__ A, const hf* __restrict__ B,
    int m0, int n0, int ldA, int ldB, int K,
    uint32_t sb, int t, int wm, int wn, int lane, float acc[2][4][4])
{
    const int nch = K >> 6;
    load_tile<false>(sb,        (const bf16*)A, m0, ldA, 0, t);
    load_tile<false>(sb + 8192, (const bf16*)B, n0, ldB, 0, t);
    CP_COMMIT();
    for (int ch = 0; ch < nch; ch++) {
        if (ch + 1 < nch) {
            const uint32_t nb = sb + ((ch + 1) & 1) * 16384;
            const int k0 = (ch + 1) << 6;
            load_tile<false>(nb,        (const bf16*)A, m0, ldA, k0, t);
            load_tile<false>(nb + 8192, (const bf16*)B, n0, ldB, k0, t);
            CP_COMMIT();
            CP_WAIT(1);
        } else {
            CP_WAIT(0);
        }
        __syncthreads();
        mma_chunk_f16(sb + (ch & 1) * 16384, acc, wm, wn, lane);
        __syncthreads();
    }
}

// ---------------- 8-warp GEMM mainloop: warp-group split-K ----------------
template <bool AT, bool BT>
__device__ __forceinline__ void gemm_main8(
    const bf16* __restrict__ Ah, const bf16* __restrict__ Al,
    const bf16* __restrict__ Bh, const bf16* __restrict__ Bl,
    int m0, int n0, int ldA, int ldB, int K,
    uint32_t sb, int t, int wg, int wm, int wn, int lane, float acc[2][4][4])
{
    const int npair = K >> 7;
    const int tl = t & 127;
    const int which = t >> 7;
    load_chunk4(sb + which * 32768, Ah, Al, Bh, Bl, m0, n0, ldA, ldB,
                which << 6, tl, AT, BT);
    CP_COMMIT();
    for (int p = 0; p < npair; p++) {
        if (p + 1 < npair) {
            load_chunk4(sb + ((p + 1) & 1) * 65536 + which * 32768, Ah, Al, Bh, Bl,
                        m0, n0, ldA, ldB, ((p + 1) << 7) + (which << 6), tl, AT, BT);
            CP_COMMIT();
            CP_WAIT(1);
        } else {
            CP_WAIT(0);
        }
        __syncthreads();
        mma_chunk<AT, BT>(sb + (p & 1) * 65536 + wg * 32768, acc, wm, wn, lane);
        __syncthreads();
    }
}

__device__ __forceinline__ void reduce8(float acc[2][4][4], float* red,
                                        int wg, int wi, int lane)
{
    if (wg == 1) {
#pragma unroll
        for (int i = 0; i < 2; i++)
#pragma unroll
            for (int j = 0; j < 4; j++) {
                const int r = i * 16 + (lane >> 2);
                const int cc = j * 8 + ((lane & 3) << 1);
                *(float2*)&red[wi * 1024 + r * 32 + cc] = make_float2(acc[i][j][0], acc[i][j][1]);
                *(float2*)&red[wi * 1024 + (r + 8) * 32 + cc] = make_float2(acc[i][j][2], acc[i][j][3]);
            }
    }
    __syncthreads();
    if (wg == 0) {
#pragma unroll
        for (int i = 0; i < 2; i++)
#pragma unroll
            for (int j = 0; j < 4; j++) {
                const int r = i * 16 + (lane >> 2);
                const int cc = j * 8 + ((lane & 3) << 1);
                const float2 v0 = *(const float2*)&red[wi * 1024 + r * 32 + cc];
                const float2 v1 = *(const float2*)&red[wi * 1024 + (r + 8) * 32 + cc];
                acc[i][j][0] += v0.x; acc[i][j][1] += v0.y;
                acc[i][j][2] += v1.x; acc[i][j][3] += v1.y;
            }
    }
}

// ---------------- epilogues ----------------
template <int EPI>
__device__ __forceinline__ void epi_store(const float acc[2][4][4],
    int m0, int n0, int N, int wm, int wn, int lane,
    float* __restrict__ C, bf16* __restrict__ Ch, bf16* __restrict__ Cl,
    const float* __restrict__ X1, float* __restrict__ U1, float* __restrict__ U2,
    float ga, float gl, float ge)
{
#pragma unroll
    for (int i = 0; i < 2; i++)
#pragma unroll
        for (int j = 0; j < 4; j++) {
            const float* a = acc[i][j];
            const int mr0 = m0 + wm * 32 + i * 16 + (lane >> 2);
            const int nc  = n0 + wn * 32 + j * 8 + ((lane & 3) << 1);
            const size_t i0 = (size_t)mr0 * N + nc;
            const size_t i1 = (size_t)(mr0 + 8) * N + nc;

            if (EPI == 0) {
                *(float2*)(C + i0) = make_float2(a[0], a[1]);
                *(float2*)(C + i1) = make_float2(a[2], a[3]);
            } else if (EPI == 1) {
                const float s0 = sigm(a[0]), s1 = sigm(a[1]);
                const float s2 = sigm(a[2]), s3 = sigm(a[3]);
                wr_hl(Ch, Cl, i0, a[0] * s0, a[1] * s1);
                wr_hl(Ch, Cl, i1, a[2] * s2, a[3] * s3);
                *(float2*)(U1 + i0) = make_float2(s0 * (1.f + a[0] * (1.f - s0)),
                                                  s1 * (1.f + a[1] * (1.f - s1)));
                *(float2*)(U1 + i1) = make_float2(s2 * (1.f + a[2] * (1.f - s2)),
                                                  s3 * (1.f + a[3] * (1.f - s3)));
            } else if (EPI == 2) {
                const float2 v0 = *(const float2*)(X1 + i0);
                const float2 v1 = *(const float2*)(X1 + i1);
                wr_hl(Ch, Cl, i0,
                      SCALE_ * fminf(fmaxf(a[0] - v0.x, -ERR_CLIP), ERR_CLIP),
                      SCALE_ * fminf(fmaxf(a[1] - v0.y, -ERR_CLIP), ERR_CLIP));
                wr_hl(Ch, Cl, i1,
                      SCALE_ * fminf(fmaxf(a[2] - v1.x, -ERR_CLIP), ERR_CLIP),
                      SCALE_ * fminf(fmaxf(a[3] - v1.y, -ERR_CLIP), ERR_CLIP));
            } else if (EPI == 3) {
                const float2 v0 = *(const float2*)(X1 + i0);
                const float2 v1 = *(const float2*)(X1 + i1);
                wr_hl(Ch, Cl, i0, a[0] * v0.x, a[1] * v0.y);
                wr_hl(Ch, Cl, i1, a[2] * v1.x, a[3] * v1.y);
            } else if (EPI == 4) {
                float2 mo0 = *(float2*)(U1 + i0), mo1 = *(float2*)(U1 + i1);
                float2 wd0 = *(float2*)(U2 + i0), wd1 = *(float2*)(U2 + i1);
                mo0.x = ge * mo0.x - gl * fminf(fmaxf(a[0], -GRAD_CLIP), GRAD_CLIP);
                mo0.y = ge * mo0.y - gl * fminf(fmaxf(a[1], -GRAD_CLIP), GRAD_CLIP);
                mo1.x = ge * mo1.x - gl * fminf(fmaxf(a[2], -GRAD_CLIP), GRAD_CLIP);
                mo1.y = ge * mo1.y - gl * fminf(fmaxf(a[3], -GRAD_CLIP), GRAD_CLIP);
                wd0.x = (1.f - ga) * wd0.x + mo0.x;
                wd0.y = (1.f - ga) * wd0.y + mo0.y;
                wd1.x = (1.f - ga) * wd1.x + mo1.x;
                wd1.y = (1.f - ga) * wd1.y + mo1.y;
                *(float2*)(U1 + i0) = mo0; *(float2*)(U1 + i1) = mo1;
                *(float2*)(U2 + i0) = wd0; *(float2*)(U2 + i1) = wd1;
                const float2 w0 = *(const float2*)(X1 + i0);
                const float2 w1 = *(const float2*)(X1 + i1);
                wr_hl(Ch, Cl, i0, w0.x + wd0.x, w0.y + wd0.y);
                wr_hl(Ch, Cl, i1, w1.x + wd1.x, w1.y + wd1.y);
            } else { // EPI 5
                wr_hl(Ch, Cl, i0, a[0] * sigm(a[0]), a[1] * sigm(a[1]));
                wr_hl(Ch, Cl, i1, a[2] * sigm(a[2]), a[3] * sigm(a[3]));
            }
        }
}

#define GSMEM   65536
#define GSMEM8  131072
#define GSMEMF  32768

// ---------------- 8-warp solo GEMM kernel (bf16x3, prologue + d1) ----------------
template <int EPI, bool AT, bool BT>
__global__ void __launch_bounds__(256)
mma_gemm8(const bf16* __restrict__ Ah, const bf16* __restrict__ Al,
          const bf16* __restrict__ Bh, const bf16* __restrict__ Bl,
          float* __restrict__ C, bf16* __restrict__ Ch, bf16* __restrict__ Cl,
          const float* __restrict__ X1, float* __restrict__ U1, float* __restrict__ U2,
          int M, int N, int K, int gate)
{
    extern __shared__ __align__(1024) char smem[];
    const int t = threadIdx.x, lane = t & 31, w = t >> 5;
    const int wg = w >> 2, wi = w & 3;
    const int wm = wi & 1, wn = wi >> 1;
    const int m0 = blockIdx.y << 6, n0 = blockIdx.x << 6;
    const uint32_t sb = smem_u32(smem);
    float acc[2][4][4] = {};
    gemm_main8<AT, BT>(Ah, Al, Bh, Bl, m0, n0, AT ? M : K, BT ? N : K, K,
                       sb, t, wg, wm, wn, lane, acc);
    reduce8(acc, (float*)smem, wg, wi, lane);
    if (wg == 0)
        epi_store<EPI>(acc, m0, n0, N, wm, wn, lane, C, Ch, Cl, X1, U1, U2, 0.f, 0.f, 0.f);
}

// ---------------- fused triple fp16 projection kernel ----------------
__global__ void __launch_bounds__(128)
mma_proj3_f16(const hf* __restrict__ A,
              const hf* __restrict__ B0, const hf* __restrict__ B1, const hf* __restrict__ B2,
              float* __restrict__ C0, float* __restrict__ C1, float* __restrict__ C2,
              int M, int N, int K)
{
    extern __shared__ __align__(1024) char smem[];
    const int t = threadIdx.x, lane = t & 31, w = t >> 5;
    const int wm = w & 1, wn = w >> 1;
    const int m0 = blockIdx.y << 6, n0 = blockIdx.x << 6;
    const hf* B = (blockIdx.z == 0) ? B0 : (blockIdx.z == 1) ? B1 : B2;
    float* C = (blockIdx.z == 0) ? C0 : (blockIdx.z == 1) ? C1 : C2;
    const uint32_t sb = smem_u32(smem);
    float acc[2][4][4] = {};
    gemm_main_f16(A, B, m0, n0, K, K, K, sb, t, wm, wn, lane, acc);
    epi_store<0>(acc, m0, n0, N, wm, wn, lane, C, nullptr, nullptr,
                 nullptr, nullptr, nullptr, 0.f, 0.f, 0.f);
}

// ---------------- solo fp16 GEMM (final output) ----------------
__global__ void __launch_bounds__(128)
mma_gemm_f16k(const hf* __restrict__ A, const hf* __restrict__ B,
              float* __restrict__ C, int M, int N, int K)
{
    extern __shared__ __align__(1024) char smem[];
    const int t = threadIdx.x, lane = t & 31, w = t >> 5;
    const int wm = w & 1, wn = w >> 1;
    const int m0 = blockIdx.y << 6, n0 = blockIdx.x << 6;
    const uint32_t sb = smem_u32(smem);
    float acc[2][4][4] = {};
    gemm_main_f16(A, B, m0, n0, K, K, K, sb, t, wm, wn, lane, acc);
    epi_store<0>(acc, m0, n0, N, wm, wn, lane, C, nullptr, nullptr,
                 nullptr, nullptr, nullptr, 0.f, 0.f, 0.f);
}

// ---------------- 4-warp dual-segment GEMM (shared B, bf16x3): tb + a1' ----------
template <int EPIa, int EPIb>
__global__ void __launch_bounds__(128)
mma_gemm_dual(const bf16* __restrict__ Aah, const bf16* __restrict__ Aal,
              const bf16* __restrict__ Abh, const bf16* __restrict__ Abl, int Ma,
              const bf16* __restrict__ Bh, const bf16* __restrict__ Bl,
              float* __restrict__ Ca, bf16* __restrict__ Cah, bf16* __restrict__ Cal,
              const float* __restrict__ X1a, float* __restrict__ U1a,
              float* __restrict__ Cb, bf16* __restrict__ Cbh, bf16* __restrict__ Cbl,
              const float* __restrict__ X1b, float* __restrict__ U1b,
              int N, int K)
{
    extern __shared__ __align__(1024) char smem[];
    const int t = threadIdx.x, lane = t & 31, w = t >> 5;
    const int wm = w & 1, wn = w >> 1;
    const int ya = Ma >> 6;
    const bool segb = (int)blockIdx.y >= ya;
    const bf16* Ah = segb ? Abh : Aah;
    const bf16* Al = segb ? Abl : Aal;
    const int m0 = (segb ? ((int)blockIdx.y - ya) : (int)blockIdx.y) << 6;
    const int n0 = blockIdx.x << 6;
    const uint32_t sb = smem_u32(smem);
    float acc[2][4][4] = {};
    gemm_main<false, false>(Ah, Al, Bh, Bl, m0, n0, K, K, K, sb, t, wm, wn, lane, acc);
    if (!segb)
        epi_store<EPIa>(acc, m0, n0, N, wm, wn, lane, Ca, Cah, Cal, X1a, U1a, nullptr,
                        0.f, 0.f, 0.f);
    else
        epi_store<EPIb>(acc, m0, n0, N, wm, wn, lane, Cb, Cbh, Cbl, X1b, U1b, nullptr,
                        0.f, 0.f, 0.f);
}

// ---------------- 8-warp dual: y (flat fp16 store) + d2'(c+1) ----------------
// grid (8, yext): by<8 -> y segment (writes g_yf directly, permuted); by>=8 -> d2'
__global__ void __launch_bounds__(256)
dual8_y_d2(const bf16* __restrict__ tbh, const bf16* __restrict__ tbl,
           const bf16* __restrict__ a1h, const bf16* __restrict__ a1l,
           const bf16* __restrict__ E2h, const bf16* __restrict__ E2l,
           const float* __restrict__ vcn, bf16* __restrict__ d2h, bf16* __restrict__ d2l,
           hf* __restrict__ yfp, int c)
{
    extern __shared__ __align__(1024) char smem[];
    const int t = threadIdx.x, lane = t & 31, w = t >> 5;
    const int wg = w >> 2, wi = w & 3;
    const int wm = wi & 1, wn = wi >> 1;
    const int by = blockIdx.y;
    const int n0 = blockIdx.x << 6;
    const uint32_t sb = smem_u32(smem);
    float acc[2][4][4] = {};
    if (by < 8) {
        const int m0 = by << 6;
        gemm_main8<false, false>(tbh, tbl, E2h, E2l, m0, n0, H_, H_, H_,
                                 sb, t, wg, wm, wn, lane, acc);
        reduce8(acc, (float*)smem, wg, wi, lane);
        if (wg == 0) {
#pragma unroll
            for (int i = 0; i < 2; i++)
#pragma unroll
                for (int j = 0; j < 4; j++) {
                    const float* a = acc[i][j];
                    const int mr0 = m0 + wm * 32 + i * 16 + (lane >> 2);
                    const int mr1 = mr0 + 8;
                    const int nc = n0 + wn * 32 + j * 8 + ((lane & 3) << 1);
                    const size_t f0 = ((size_t)(mr0 >> 6) * S_ + c * CS_ + (mr0 & 63)) * D_ + nc;
                    const size_t f1 = ((size_t)(mr1 >> 6) * S_ + c * CS_ + (mr1 & 63)) * D_ + nc;
                    *(__half2*)(yfp + f0) = __floats2half2_rn(a[0], a[1]);
                    *(__half2*)(yfp + f1) = __floats2half2_rn(a[2], a[3]);
                }
        }
    } else {
        const int m0 = (by - 8) << 6;
        gemm_main8<false, false>(a1h, a1l, E2h, E2l, m0, n0, H_, H_, H_,
                                 sb, t, wg, wm, wn, lane, acc);
        reduce8(acc, (float*)smem, wg, wi, lane);
        if (wg == 0)
            epi_store<2>(acc, m0, n0, D_, wm, wn, lane, nullptr, d2h, d2l,
                         vcn, nullptr, nullptr, 0.f, 0.f, 0.f);
    }
}

// ---------------- fused dual-update kernel (4-warp; 256 CTAs) ----------------
__global__ void __launch_bounds__(128)
mma_update_dual(const bf16* __restrict__ d2h, const bf16* __restrict__ d2l,
                const bf16* __restrict__ a1h, const bf16* __restrict__ a1l,
                const bf16* __restrict__ d1h, const bf16* __restrict__ d1l,
                const bf16* __restrict__ kchp, const bf16* __restrict__ kclp,
                const float* __restrict__ W2, float* __restrict__ M2,
                float* __restrict__ Wd2, bf16* __restrict__ E2h, bf16* __restrict__ E2l,
                const float* __restrict__ W1, float* __restrict__ M1,
                float* __restrict__ Wd1, bf16* __restrict__ E1h, bf16* __restrict__ E1l,
                int gate)
{
    extern __shared__ __align__(1024) char smem[];
    const int t = threadIdx.x, lane = t & 31, w = t >> 5;
    const int wm = w & 1, wn = w >> 1;
    const int bid = blockIdx.x;
    const bool segb = bid >= 128;
    const uint32_t sb = smem_u32(smem);
    const float ga = g_alpha[gate], gl = g_lrg[gate], ge = g_eta[gate];
    float acc[2][4][4] = {};
    if (!segb) {
        const int n0 = (bid & 15) << 6, m0 = (bid >> 4) << 6;
        gemm_main<true, true>(d2h, d2l, a1h, a1l, m0, n0, D_, H_, R_,
                              sb, t, wm, wn, lane, acc);
        epi_store<4>(acc, m0, n0, H_, wm, wn, lane, nullptr, E2h, E2l, W2, M2, Wd2,
                     ga, gl, ge);
    } else {
        const int r = bid - 128;
        const int n0 = (r & 7) << 6, m0 = (r >> 3) << 6;
        gemm_main<true, true>(d1h, d1l, kchp, kclp, m0, n0, H_, D_, R_,
                              sb, t, wm, wn, lane, acc);
        epi_store<4>(acc, m0, n0, D_, wm, wn, lane, nullptr, E1h, E1l, W1, M1, Wd1,
                     ga, gl, ge);
    }
}

template <int EPI, bool AT, bool BT>
static void run8(const bf16* Ah, const bf16* Al, const bf16* Bh, const bf16* Bl,
                 float* C, bf16* Ch, bf16* Cl,
                 const float* X1, float* U1, float* U2, int M, int N, int K, int gate)
{
    cudaFuncSetAttribute(mma_gemm8<EPI, AT, BT>,
                         cudaFuncAttributeMaxDynamicSharedMemorySize, GSMEM8);
    dim3 grid(N >> 6, M >> 6);
    mma_gemm8<EPI, AT, BT><<<grid, 256, GSMEM8>>>(Ah, Al, Bh, Bl, C, Ch, Cl, X1, U1, U2,
                                                  M, N, K, gate);
}

// ---------------- misc kernels ----------------
__global__ void init_kernel(const float* __restrict__ W1, const float* __restrict__ W2)
{
    const size_t i = ((size_t)blockIdx.x * blockDim.x + threadIdx.x) * 2;
    if (i >= (size_t)H_ * D_) return;
    *(float2*)(g_Wd1 + i) = make_float2(0.f, 0.f);
    *(float2*)(g_M1  + i) = make_float2(0.f, 0.f);
    *(float2*)(g_Wd2 + i) = make_float2(0.f, 0.f);
    *(float2*)(g_M2  + i) = make_float2(0.f, 0.f);
    const float2 w1 = *(const float2*)(W1 + i);
    const float2 w2 = *(const float2*)(W2 + i);
    wr_hl(g_E1h, g_E1l, i, w1.x, w1.y);
    wr_hl(g_E2h, g_E2l, i, w2.x, w2.y);
}

// fused fp16 conversion: x (BS*D) + 4 weight matrices (D*D)
__global__ void cvt_all_kernel(const float* __restrict__ x,
                               const float* __restrict__ Wk, const float* __restrict__ Wv,
                               const float* __restrict__ Wq, const float* __restrict__ Wo)
{
    const int i = blockIdx.x * blockDim.x + threadIdx.x;
    const int nT2 = BS_ * D_ / 2;
    const int nD2 = D_ * D_ / 2;
    if (i < nT2) {
        const float2 v = ((const float2*)x)[i];
        *(__half2*)(g_xf + (size_t)i * 2) = __floats2half2_rn(v.x, v.y);
    }
    if (i < nD2) {
        const float2 a = ((const float2*)Wk)[i];
        const float2 b = ((const float2*)Wv)[i];
        const float2 cq = ((const float2*)Wq)[i];
        const float2 d = ((const float2*)Wo)[i];
        *(__half2*)(g_Wkf + (size_t)i * 2) = __floats2half2_rn(a.x, a.y);
        *(__half2*)(g_Wvf + (size_t)i * 2) = __floats2half2_rn(b.x, b.y);
        *(__half2*)(g_Wqf + (size_t)i * 2) = __floats2half2_rn(cq.x, cq.y);
        *(__half2*)(g_Wof + (size_t)i * 2) = __floats2half2_rn(d.x, d.y);
    }
}

// fused causal depthwise conv for k, v, q -> chunk-major [NC][R][D]
__global__ void conv3_kernel(const float* __restrict__ wk, const float* __restrict__ bk,
                             const float* __restrict__ wv, const float* __restrict__ bv,
                             const float* __restrict__ wq, const float* __restrict__ bq)
{
    const size_t i = (size_t)blockIdx.x * blockDim.x + threadIdx.x;
    if (i >= (size_t)BS_ * D_) return;
    const int d = (int)(i & (D_ - 1));
    const size_t bs = i >> 9;
    const int s = (int)(bs & (S_ - 1));
    const int b = (int)(bs >> 12);
    float ak = bk[d], av = bv[d], aq = bq[d];
#pragma unroll
    for (int j = 0; j < Kc_; j++) {
        const int sp = s - (Kc_ - 1) + j;
        if (sp >= 0) {
            const size_t idx = ((size_t)b * S_ + sp) * D_ + d;
            ak = fmaf(wk[d * Kc_ + j], g_pk[idx], ak);
            av = fmaf(wv[d * Kc_ + j], g_pv[idx], av);
            aq = fmaf(wq[d * Kc_ + j], g_pq[idx], aq);
        }
    }
    const int c  = s >> 6;
    const int cs = s & 63;
    const size_t o = (((size_t)c * R_ + (b * CS_ + cs)) << 9) + d;
    {
        const bf16 hv = __float2bfloat16_rn(ak);
        g_kch[o] = hv;
        g_kcl[o] = __float2bfloat16_rn(ak - __bfloat162float(hv));
    }
    g_vc[o] = av;
    {
        const bf16 hv = __float2bfloat16_rn(aq);
        g_qch[o] = hv;
        g_qcl[o] = __float2bfloat16_rn(aq - __bfloat162float(hv));
    }
}

__global__ void gates_kernel(const float* __restrict__ x,
                             const float* __restrict__ wd, const float* __restrict__ bd,
                             const float* __restrict__ wl, const float* __restrict__ bl,
                             const float* __restrict__ we, const float* __restrict__ be)
{
    const int c = blockIdx.x;
    const int t = threadIdx.x;
    const int b  = t >> 6;
    const int cs = t & 63;
    const float4* xr = (const float4*)(x + (((size_t)b * S_ + (size_t)c * CS_ + cs) << 9));
    const float4* w0 = (const float4*)wd;
    const float4* w1 = (const float4*)wl;
    const float4* w2 = (const float4*)we;
    float s0 = 0.f, s1 = 0.f, s2 = 0.f;
#pragma unroll 4
    for (int d = 0; d < D_ / 4; d++) {
        const float4 xv = xr[d];
        const float4 a0 = w0[d], a1 = w1[d], a2 = w2[d];
        s0 += xv.x * a0.x + xv.y * a0.y + xv.z * a0.z + xv.w * a0.w;
        s1 += xv.x * a1.x + xv.y * a1.y + xv.z * a1.z + xv.w * a1.w;
        s2 += xv.x * a2.x + xv.y * a2.y + xv.z * a2.z + xv.w * a2.w;
    }
    s0 = sigm(s0 + bd[0]);
    s1 = sigm(s1 + bl[0]);
    s2 = sigm(s2 + be[0]);

    __shared__ float r0[512], r1[512], r2[512];
    r0[t] = s0; r1[t] = s1; r2[t] = s2;
    __syncthreads();
    for (int off = 256; off > 0; off >>= 1) {
        if (t < off) { r0[t] += r0[t + off]; r1[t] += r1[t + off]; r2[t] += r2[t + off]; }
        __syncthreads();
    }
    if (t == 0) {
        g_alpha[c] = r0[0] * (1.0f / 512.0f);
        g_lrg[c]   = r1[0] * (1.0f / 512.0f);
        g_eta[c]   = r2[0] * (1.0f / 512.0f);
    }
}

// ---------------- entry point ----------------
extern "C" void kernel_launch(void* const* d_in, const int* in_sizes, int n_in,
                              void* d_out, int out_size)
{
    (void)in_sizes; (void)n_in; (void)out_size;
    const float* x    = (const float*)d_in[0];
    const float* Wk   = (const float*)d_in[1];
    const float* Wv   = (const float*)d_in[2];
    const float* Wq   = (const float*)d_in[3];
    const float* Wout = (const float*)d_in[4];
    const float* ckw  = (const float*)d_in[5];
    const float* ckb  = (const float*)d_in[6];
    const float* cvw  = (const float*)d_in[7];
    const float* cvb  = (const float*)d_in[8];
    const float* cqw  = (const float*)d_in[9];
    const float* cqb  = (const float*)d_in[10];
    const float* wdec = (const float*)d_in[11];
    const float* bdec = (const float*)d_in[12];
    const float* wlr  = (const float*)d_in[13];
    const float* blr  = (const float*)d_in[14];
    const float* weta = (const float*)d_in[15];
    const float* beta = (const float*)d_in[16];
    const float* W1   = (const float*)d_in[17];
    const float* W2   = (const float*)d_in[18];
    float* out = (float*)d_out;

    float *pk, *pv, *pq, *vc, *sd, *Wd1, *M1, *Wd2, *M2;
    bf16 *kch, *kcl, *qch, *qcl, *a1h, *a1l, *d2h, *d2l, *d1h, *d1l, *tbh, *tbl;
    bf16 *E1h, *E1l, *E2h, *E2l;
    hf *xf, *yf, *Wkf, *Wvf, *Wqf, *Wof;
    cudaGetSymbolAddress((void**)&pk,  g_pk);
    cudaGetSymbolAddress((void**)&pv,  g_pv);
    cudaGetSymbolAddress((void**)&pq,  g_pq);
    cudaGetSymbolAddress((void**)&vc,  g_vc);
    cudaGetSymbolAddress((void**)&sd,  g_sd);
    cudaGetSymbolAddress((void**)&Wd1, g_Wd1);
    cudaGetSymbolAddress((void**)&M1,  g_M1);
    cudaGetSymbolAddress((void**)&Wd2, g_Wd2);
    cudaGetSymbolAddress((void**)&M2,  g_M2);
    cudaGetSymbolAddress((void**)&xf,  g_xf);  cudaGetSymbolAddress((void**)&yf,  g_yf);
    cudaGetSymbolAddress((void**)&kch, g_kch); cudaGetSymbolAddress((void**)&kcl, g_kcl);
    cudaGetSymbolAddress((void**)&qch, g_qch); cudaGetSymbolAddress((void**)&qcl, g_qcl);
    cudaGetSymbolAddress((void**)&a1h, g_a1h); cudaGetSymbolAddress((void**)&a1l, g_a1l);
    cudaGetSymbolAddress((void**)&d2h, g_d2h); cudaGetSymbolAddress((void**)&d2l, g_d2l);
    cudaGetSymbolAddress((void**)&d1h, g_d1h); cudaGetSymbolAddress((void**)&d1l, g_d1l);
    cudaGetSymbolAddress((void**)&tbh, g_tbh); cudaGetSymbolAddress((void**)&tbl, g_tbl);
    cudaGetSymbolAddress((void**)&E1h, g_E1h); cudaGetSymbolAddress((void**)&E1l, g_E1l);
    cudaGetSymbolAddress((void**)&E2h, g_E2h); cudaGetSymbolAddress((void**)&E2l, g_E2l);
    cudaGetSymbolAddress((void**)&Wkf, g_Wkf); cudaGetSymbolAddress((void**)&Wvf, g_Wvf);
    cudaGetSymbolAddress((void**)&Wqf, g_Wqf); cudaGetSymbolAddress((void**)&Wof, g_Wof);

    const int nRD = R_ * D_;
    const int nHD = H_ * D_;
    const int nTOT = BS_ * D_;

    init_kernel<<<(nHD / 2 + 255) / 256, 256>>>(W1, W2);
    gates_kernel<<<NC_, 512>>>(x, wdec, bdec, wlr, blr, weta, beta);
    cvt_all_kernel<<<(nTOT / 2 + 255) / 256, 256>>>(x, Wk, Wv, Wq, Wout);

    // fused triple projection (fp16 1-pass), then fused triple conv
    cudaFuncSetAttribute(mma_proj3_f16, cudaFuncAttributeMaxDynamicSharedMemorySize, GSMEMF);
    mma_proj3_f16<<<dim3(D_ >> 6, BS_ >> 6, 3), 128, GSMEMF>>>(
        xf, Wkf, Wvf, Wqf, pk, pv, pq, BS_, D_, D_);
    conv3_kernel<<<(nTOT + 255) / 256, 256>>>(ckw, ckb, cvw, cvb, cqw, cqb);

    cudaFuncSetAttribute(mma_gemm_dual<5, 1>,
                         cudaFuncAttributeMaxDynamicSharedMemorySize, GSMEM);
    cudaFuncSetAttribute(dual8_y_d2,
                         cudaFuncAttributeMaxDynamicSharedMemorySize, GSMEM8);
    cudaFuncSetAttribute(mma_update_dual,
                         cudaFuncAttributeMaxDynamicSharedMemorySize, GSMEM);

    // prologue: a1(0)+sd(0) with E1=W1; d2(0) with E2=W2  (bf16x3, 8-warp)
    run8<1, false, false>(kch, kcl, E1h, E1l, nullptr, a1h, a1l,
                          nullptr, sd, nullptr, R_, H_, D_, 0);
    run8<2, false, false>(a1h, a1l, E2h, E2l, nullptr, d2h, d2l,
                          vc, nullptr, nullptr, R_, D_, H_, 0);

    for (int c = 0; c < NC_; c++) {
        const size_t off  = (size_t)c * nRD;
        const size_t offn = (size_t)(c + 1) * nRD;
        const int yext = (c + 1 < NC_) ? 16 : 8;

        // d1(c) = (d2 E2_old) * sd    — 128 CTAs, 8-warp split-K
        run8<3, false, true>(d2h, d2l, E2h, E2l, nullptr, d1h, d1l,
                             sd, nullptr, nullptr, R_, H_, D_, 0);
        // fused updates: g2 -> E2 new ; g1 -> E1 new (256 CTAs, 4-warp)
        mma_update_dual<<<256, 128, GSMEM>>>(d2h, d2l, a1h, a1l, d1h, d1l,
                                             kch + off, kcl + off,
                                             W2, M2, Wd2, E2h, E2l,
                                             W1, M1, Wd1, E1h, E1l, c);
        // fused: tb(c) = silu(Qc E1^T) [+ a1,sd(c+1)]
        mma_gemm_dual<5, 1><<<dim3(H_ >> 6, yext), 128, GSMEM>>>(
            qch + off, qcl + off, kch + offn, kcl + offn, R_,
            E1h, E1l,
            nullptr, tbh, tbl, nullptr, nullptr,
            nullptr, a1h, a1l, nullptr, sd,
            H_, D_);
        // fused: y(c) -> flat fp16 yf [+ d2(c+1)]  (K=1024, 8-warp)
        dual8_y_d2<<<dim3(D_ >> 6, yext), 256, GSMEM8>>>(
            tbh, tbl, a1h, a1l, E2h, E2l,
            vc + offn, d2h, d2l, yf, c);
    }

    // final output GEMM: out = yf * Wout^T (fp16 1-pass)
    cudaFuncSetAttribute(mma_gemm_f16k, cudaFuncAttributeMaxDynamicSharedMemorySize, GSMEMF);
    mma_gemm_f16k<<<dim3(D_ >> 6, BS_ >> 6), 128, GSMEMF>>>(yf, Wof, out, BS_, D_, D_);
}